// round 10
// baseline (speedup 1.0000x reference)
#include <cuda_runtime.h>
#include <cuda_fp16.h>
#include <math.h>
#include <stdint.h>

// ----------------------------------------------------------------------------
// GATv2 Transformer. GEMMs: fp16 mma.sync, A split hi+lo, weights fp16,
// cp.async double buffer, LN fused into N=128 epilogues. xlr stored packed
// half2 (halves gather + write traffic). Edge phase: CSR + online softmax.
// ----------------------------------------------------------------------------

#define MAXN 50000
#define MAXE 800000
#define DIM 128
#define HD 256
#define MLPD 512
#define LWORDS 114688

// ------------------------- scratch (device globals) -------------------------
__device__ __align__(256) uint32_t g_xlr [(size_t)MAXN * 256];   // half2-packed [xl|xr]
__device__ __align__(256) uint32_t g_h_hi [(size_t)MAXN * (DIM/2)];
__device__ __align__(256) uint32_t g_h_lo [(size_t)MAXN * (DIM/2)];
__device__ __align__(256) uint32_t g_go_hi[(size_t)MAXN * (HD/2)];
__device__ __align__(256) uint32_t g_go_lo[(size_t)MAXN * (HD/2)];
__device__ __align__(256) uint32_t g_mid_hi[(size_t)MAXN * (MLPD/2)];
__device__ __align__(256) uint32_t g_mid_lo[(size_t)MAXN * (MLPD/2)];
__device__ __align__(256) uint32_t g_wb[2 * LWORDS];
__device__ __align__(256) float    g_blr[2 * 512];
// CSR
__device__ __align__(256) int g_src[MAXE];
__device__ __align__(256) int g_dst[MAXE];
__device__ __align__(256) int g_esrc[MAXE];
__device__ __align__(256) int g_deg[MAXN];
__device__ __align__(256) int g_off[MAXN + 1];
__device__ __align__(256) int g_pos[MAXN];
__device__ __align__(256) int g_bsum[64];
__device__ __align__(256) int g_boff[64];
__device__ int g_is64;

// ------------------------- helpers -------------------------
__device__ __forceinline__ void split_pack(float x, float y, uint32_t& hi, uint32_t& lo) {
    __half hx = __float2half_rn(x);
    __half hy = __float2half_rn(y);
    __half lx = __float2half_rn(x - __half2float(hx));
    __half ly = __float2half_rn(y - __half2float(hy));
    hi = ((uint32_t)__half_as_ushort(hy) << 16) | (uint32_t)__half_as_ushort(hx);
    lo = ((uint32_t)__half_as_ushort(ly) << 16) | (uint32_t)__half_as_ushort(lx);
}
__device__ __forceinline__ uint32_t pack_h(float x, float y) {
    return ((uint32_t)__half_as_ushort(__float2half_rn(y)) << 16)
         | (uint32_t)__half_as_ushort(__float2half_rn(x));
}
__device__ __forceinline__ float4 h2f4(uint2 w) {
    float2 a = __half22float2(*(__half2*)&w.x);
    float2 b = __half22float2(*(__half2*)&w.y);
    return make_float4(a.x, a.y, b.x, b.y);
}

// ------------------------- edge dtype detect / decode+hist -------------------
__global__ void detect_kernel(const void* edges, int E, int N) {
    __shared__ int bad;
    if (threadIdx.x == 0) bad = 0;
    __syncthreads();
    const long long* p = (const long long*)edges;
    int n = E < 2048 ? E : 2048;
    for (int i = threadIdx.x; i < n; i += blockDim.x) {
        long long v = p[i];
        if (v < 0 || v >= (long long)N) atomicOr(&bad, 1);
    }
    __syncthreads();
    if (threadIdx.x == 0) g_is64 = bad ? 0 : 1;
}

__global__ void clear_deg_kernel(int N) {
    int i = blockIdx.x * blockDim.x + threadIdx.x;
    if (i < N) g_deg[i] = 0;
}

__global__ void decode_hist_kernel(const void* edges, int E) {
    int i = blockIdx.x * blockDim.x + threadIdx.x;
    if (i >= E) return;
    int s, d;
    if (g_is64) {
        const long long* p = (const long long*)edges;
        s = (int)p[i];
        d = (int)p[(size_t)E + i];
    } else {
        const int* p = (const int*)edges;
        s = p[i];
        d = p[(size_t)E + i];
    }
    g_src[i] = s;
    g_dst[i] = d;
    atomicAdd(&g_deg[d], 1);
}

// ---- 3-phase parallel scan ----
__global__ void scanA_kernel(int N) {
    int t = threadIdx.x;
    int i = blockIdx.x * 1024 + t;
    int lane = t & 31, w = t >> 5;
    int v = (i < N) ? g_deg[i] : 0;
    int s = v;
    #pragma unroll
    for (int o = 1; o < 32; o <<= 1) {
        int u = __shfl_up_sync(0xffffffffu, s, o);
        if (lane >= o) s += u;
    }
    __shared__ int wt[32];
    if (lane == 31) wt[w] = s;
    __syncthreads();
    if (w == 0) {
        int x = wt[lane];
        #pragma unroll
        for (int o = 1; o < 32; o <<= 1) {
            int u = __shfl_up_sync(0xffffffffu, x, o);
            if (lane >= o) x += u;
        }
        wt[lane] = x;
    }
    __syncthreads();
    if (w) s += wt[w - 1];
    if (i < N) g_off[i + 1] = s;
    if (t == 1023) g_bsum[blockIdx.x] = s;
}

__global__ void scanB_kernel(int nb) {
    int lane = threadIdx.x;
    int v0 = (lane < nb) ? g_bsum[lane] : 0;
    int v1 = (32 + lane < nb) ? g_bsum[32 + lane] : 0;
    int s0 = v0;
    #pragma unroll
    for (int o = 1; o < 32; o <<= 1) {
        int u = __shfl_up_sync(0xffffffffu, s0, o);
        if (lane >= o) s0 += u;
    }
    int tot0 = __shfl_sync(0xffffffffu, s0, 31);
    int s1 = v1;
    #pragma unroll
    for (int o = 1; o < 32; o <<= 1) {
        int u = __shfl_up_sync(0xffffffffu, s1, o);
        if (lane >= o) s1 += u;
    }
    if (lane < nb) g_boff[lane] = s0 - v0;
    if (32 + lane < nb) g_boff[32 + lane] = tot0 + s1 - v1;
}

__global__ void scanC_kernel(int N) {
    int i = blockIdx.x * blockDim.x + threadIdx.x;
    if (i == 0) g_off[0] = 0;
    if (i >= N) return;
    int b = i >> 10;
    int inc = g_off[i + 1] + g_boff[b];
    g_off[i + 1] = inc;
    g_pos[i] = inc - g_deg[i];
}

__global__ void scatter_kernel(int E) {
    int i = blockIdx.x * blockDim.x + threadIdx.x;
    if (i >= E) return;
    int p = atomicAdd(&g_pos[g_dst[i]], 1);
    g_esrc[p] = g_src[i];
}

// ---------------- fused weight convert (single fp16) -------------------------
__global__ void wconv_all_kernel(const float* __restrict__ Wl, const float* __restrict__ Wr,
                                 const float* __restrict__ pj, const float* __restrict__ W1,
                                 const float* __restrict__ W2) {
    int idx = blockIdx.x * blockDim.x + threadIdx.x;
    if (idx >= 2 * LWORDS) return;
    int layer = idx / LWORDS;
    int r = idx - layer * LWORDS;
    const float* W; int K, N;
    if (r < 16384)      { W = Wl + (size_t)layer * 32768; K = 128; N = 256; }
    else if (r < 32768) { W = Wr + (size_t)layer * 32768; r -= 16384; K = 128; N = 256; }
    else if (r < 49152) { W = pj + (size_t)layer * 32768; r -= 32768; K = 256; N = 128; }
    else if (r < 81920) { W = W1 + (size_t)layer * 65536; r -= 49152; K = 128; N = 512; }
    else                { W = W2 + (size_t)layer * 65536; r -= 81920; K = 512; N = 128; }
    int kw = K >> 1;
    int n = r / kw, kp = r - n * kw;
    float x = W[(size_t)(2 * kp) * N + n];
    float y = W[(size_t)(2 * kp + 1) * N + n];
    g_wb[idx] = pack_h(x, y);
}

__global__ void bconcat_kernel(const float* __restrict__ bl, const float* __restrict__ br) {
    int i = threadIdx.x + blockIdx.x * blockDim.x;
    if (i >= 1024) return;
    int layer = i >> 9, j = i & 511;
    float v = (j < 256) ? bl[layer * HD + j] : br[layer * HD + j - 256];
    g_blr[layer * 512 + j] = v;
}

// ------------------------- standalone layernorm ------------------------------
__global__ void ln_kernel(const float* __restrict__ x, const float* __restrict__ g,
                          const float* __restrict__ b,
                          uint32_t* __restrict__ ohi, uint32_t* __restrict__ olo, int N) {
    int row = (blockIdx.x * blockDim.x + threadIdx.x) >> 5;
    int lane = threadIdx.x & 31;
    if (row >= N) return;
    const float4* xr = (const float4*)x + (size_t)row * 32;
    float4 v = xr[lane];
    float s  = v.x + v.y + v.z + v.w;
    float sq = v.x*v.x + v.y*v.y + v.z*v.z + v.w*v.w;
    #pragma unroll
    for (int o = 16; o; o >>= 1) {
        s  += __shfl_xor_sync(0xffffffffu, s,  o);
        sq += __shfl_xor_sync(0xffffffffu, sq, o);
    }
    float m   = s * (1.0f / 128.0f);
    float var = sq * (1.0f / 128.0f) - m * m;
    float inv = rsqrtf(var + 1e-5f);
    float4 gg = ((const float4*)g)[lane];
    float4 bb = ((const float4*)b)[lane];
    float o0 = (v.x - m) * inv * gg.x + bb.x;
    float o1 = (v.y - m) * inv * gg.y + bb.y;
    float o2 = (v.z - m) * inv * gg.z + bb.z;
    float o3 = (v.w - m) * inv * gg.w + bb.w;
    uint32_t h0, l0, h1, l1;
    split_pack(o0, o1, h0, l0);
    split_pack(o2, o3, h1, l1);
    size_t base = (size_t)row * 64 + lane * 2;
    ohi[base] = h0; ohi[base + 1] = h1;
    olo[base] = l0; olo[base + 1] = l1;
}

// ------------------------- tensor-core GEMM --------------------------------
__device__ __forceinline__ void mma16816(float* c, const uint32_t* a, const uint32_t* b) {
    asm volatile(
        "mma.sync.aligned.m16n8k16.row.col.f32.f16.f16.f32 "
        "{%0,%1,%2,%3}, {%4,%5,%6,%7}, {%8,%9}, {%0,%1,%2,%3};"
        : "+f"(c[0]), "+f"(c[1]), "+f"(c[2]), "+f"(c[3])
        : "r"(a[0]), "r"(a[1]), "r"(a[2]), "r"(a[3]), "r"(b[0]), "r"(b[1]));
}

__device__ __forceinline__ void cpa16(uint32_t dst, const void* src, int bytes) {
    asm volatile("cp.async.cg.shared.global [%0], [%1], 16, %2;\n"
                 :: "r"(dst), "l"(src), "r"(bytes));
}

__device__ __forceinline__ int swz(int row, int kp) {
    return (row << 4) | (((kp >> 2) ^ ((row >> 1) & 3)) << 2) | (kp & 3);
}

#define TILE_WORDS 2048
#define BUF_WORDS  (3 * TILE_WORDS)
#define GEMM_SMEM  (2 * BUF_WORDS * 4)       // 48 KB
#define GEMM_SMEM3 65536                     // MODE 3 rowbuf

// MODE 0: store fp32; 1: accumulate fp32; 2: GELU then split hi/lo;
// MODE 3: accumulate + fused LN -> x and split h; MODE 4: store packed half2
template<int MODE>
__global__ __launch_bounds__(256, 2)
void gemm_kernel(const uint32_t* __restrict__ Ahi, const uint32_t* __restrict__ Alo,
                 const uint32_t* __restrict__ Bh_g,
                 const float* __restrict__ bias, float* __restrict__ C,
                 uint32_t* __restrict__ Chi, uint32_t* __restrict__ Clo,
                 const float* __restrict__ lng, const float* __restrict__ lnb,
                 int M, int K, int N) {
    extern __shared__ uint32_t sm[];

    const int tid  = threadIdx.x;
    const int lane = tid & 31;
    const int wid  = tid >> 5;
    const int warp_m = wid & 3;
    const int warp_n = wid >> 2;
    const int m0 = blockIdx.y * 128, n0 = blockIdx.x * 128;
    const int g  = lane >> 2;
    const int tg = lane & 3;
    const int kw = K >> 1;
    const int nk = K >> 5;

    const uint32_t sbase = (uint32_t)__cvta_generic_to_shared(sm);

    float acc[2][8][4];
    #pragma unroll
    for (int i = 0; i < 2; i++)
        #pragma unroll
        for (int j = 0; j < 8; j++)
            #pragma unroll
            for (int r = 0; r < 4; r++) acc[i][j][r] = 0.0f;

    auto issue = [&](int kt, int b) {
        uint32_t bufb = sbase + (uint32_t)(b * BUF_WORDS) * 4;
        #pragma unroll
        for (int t = 0; t < 2; t++) {
            int chunk = tid + t * 256;
            int row = chunk >> 2, c = chunk & 3;
            int dstw = (row << 4) | ((c ^ ((row >> 1) & 3)) << 2);
            int asz = (m0 + row < M) ? 16 : 0;
            const uint32_t* asrc = Ahi + (size_t)(m0 + row) * kw + kt * 16 + c * 4;
            const uint32_t* alsr = Alo + (size_t)(m0 + row) * kw + kt * 16 + c * 4;
            const uint32_t* bsrc = Bh_g + (size_t)(n0 + row) * kw + kt * 16 + c * 4;
            cpa16(bufb + (uint32_t)dstw * 4,                    asrc, asz);
            cpa16(bufb + (uint32_t)(TILE_WORDS + dstw) * 4,     alsr, asz);
            cpa16(bufb + (uint32_t)(2 * TILE_WORDS + dstw) * 4, bsrc, 16);
        }
        asm volatile("cp.async.commit_group;\n");
    };

    issue(0, 0);

    for (int kt = 0; kt < nk; kt++) {
        const bool more = (kt + 1 < nk);
        if (more) issue(kt + 1, (kt + 1) & 1);
        if (more) { asm volatile("cp.async.wait_group 1;\n"); }
        else      { asm volatile("cp.async.wait_group 0;\n"); }
        __syncthreads();

        const uint32_t* Ah = sm + (kt & 1) * BUF_WORDS;
        const uint32_t* Al = Ah + TILE_WORDS;
        const uint32_t* Bh = Ah + 2 * TILE_WORDS;
        #pragma unroll
        for (int ks = 0; ks < 2; ks++) {
            const int kb = ks * 4;
            uint32_t ah[2][4], al[2][4];
            #pragma unroll
            for (int mt = 0; mt < 2; mt++) {
                int r0 = warp_m * 32 + mt * 16;
                ah[mt][0] = Ah[swz(r0 + g,     kb + tg)];
                ah[mt][1] = Ah[swz(r0 + g + 8, kb + tg)];
                ah[mt][2] = Ah[swz(r0 + g,     kb + tg + 8)];
                ah[mt][3] = Ah[swz(r0 + g + 8, kb + tg + 8)];
                al[mt][0] = Al[swz(r0 + g,     kb + tg)];
                al[mt][1] = Al[swz(r0 + g + 8, kb + tg)];
                al[mt][2] = Al[swz(r0 + g,     kb + tg + 8)];
                al[mt][3] = Al[swz(r0 + g + 8, kb + tg + 8)];
            }
            #pragma unroll
            for (int nt = 0; nt < 8; nt++) {
                int col = warp_n * 64 + nt * 8 + g;
                uint32_t bh[2];
                bh[0] = Bh[swz(col, kb + tg)];
                bh[1] = Bh[swz(col, kb + tg + 8)];
                #pragma unroll
                for (int mt = 0; mt < 2; mt++) {
                    float* c = acc[mt][nt];
                    mma16816(c, ah[mt], bh);
                    mma16816(c, al[mt], bh);
                }
            }
        }
        __syncthreads();
    }

    // ---- epilogue ----
    float* rowbuf = (float*)sm;
    #pragma unroll
    for (int mt = 0; mt < 2; mt++) {
        int rloc = warp_m * 32 + mt * 16 + (lane >> 2);
        int row = m0 + rloc;
        #pragma unroll
        for (int nt = 0; nt < 8; nt++) {
            int col = n0 + warp_n * 64 + nt * 8 + (lane & 3) * 2;
            float2 bb = *(const float2*)(bias + col);
            #pragma unroll
            for (int half = 0; half < 2; half++) {
                int r = row + half * 8;
                if (r >= M) continue;
                float v0 = acc[mt][nt][2 * half]     + bb.x;
                float v1 = acc[mt][nt][2 * half + 1] + bb.y;
                if (MODE == 2) {
                    float u = v0;
                    v0 = 0.5f * u * (1.0f + tanhf(0.7978845608028654f * (u + 0.044715f * u * u * u)));
                    u = v1;
                    v1 = 0.5f * u * (1.0f + tanhf(0.7978845608028654f * (u + 0.044715f * u * u * u)));
                    uint32_t h, l;
                    split_pack(v0, v1, h, l);
                    size_t w = (size_t)r * (N >> 1) + (col >> 1);
                    Chi[w] = h; Clo[w] = l;
                } else if (MODE == 4) {
                    Chi[(size_t)r * (N >> 1) + (col >> 1)] = pack_h(v0, v1);
                } else if (MODE == 3) {
                    float2 old = *(float2*)(C + (size_t)r * N + col);
                    rowbuf[(rloc + half * 8) * 128 + (col - n0)]     = v0 + old.x;
                    rowbuf[(rloc + half * 8) * 128 + (col - n0) + 1] = v1 + old.y;
                } else {
                    float2* dst = (float2*)(C + (size_t)r * N + col);
                    if (MODE == 1) {
                        float2 old = *dst;
                        v0 += old.x; v1 += old.y;
                    }
                    *dst = make_float2(v0, v1);
                }
            }
        }
    }

    if (MODE == 3) {
        __syncthreads();
        float4 gg = ((const float4*)lng)[lane];
        float4 bb2 = ((const float4*)lnb)[lane];
        for (int rr = wid * 16; rr < wid * 16 + 16; rr++) {
            int r = m0 + rr;
            if (r >= M) break;
            float4 v = ((const float4*)(rowbuf + rr * 128))[lane];
            float s  = v.x + v.y + v.z + v.w;
            float sq = v.x*v.x + v.y*v.y + v.z*v.z + v.w*v.w;
            #pragma unroll
            for (int o = 16; o; o >>= 1) {
                s  += __shfl_xor_sync(0xffffffffu, s,  o);
                sq += __shfl_xor_sync(0xffffffffu, sq, o);
            }
            float m   = s * (1.0f / 128.0f);
            float var = sq * (1.0f / 128.0f) - m * m;
            float inv = rsqrtf(var + 1e-5f);
            ((float4*)(C + (size_t)r * 128))[lane] = v;
            float o0 = (v.x - m) * inv * gg.x + bb2.x;
            float o1 = (v.y - m) * inv * gg.y + bb2.y;
            float o2 = (v.z - m) * inv * gg.z + bb2.z;
            float o3 = (v.w - m) * inv * gg.w + bb2.w;
            uint32_t h0, l0, h1, l1;
            split_pack(o0, o1, h0, l0);
            split_pack(o2, o3, h1, l1);
            size_t base = (size_t)r * 64 + lane * 2;
            Chi[base] = h0; Chi[base + 1] = h1;
            Clo[base] = l0; Clo[base + 1] = l1;
        }
    }
}

// ------------------- fused GATv2 node kernel (warp per dst) ------------------
// xlr packed half2: row = 256 words [xl h0 | xl h1 | xr h0 | xr h1] x 64 words.
__global__ void gat_node_kernel(const uint32_t* __restrict__ xlr,
                                const float* __restrict__ att,
                                const float* __restrict__ gat_b,
                                uint32_t* __restrict__ gohi, uint32_t* __restrict__ golo,
                                int N) {
    int node = (blockIdx.x * blockDim.x + threadIdx.x) >> 5;
    int lane = threadIdx.x & 31;
    if (node >= N) return;

    float4 r0 = h2f4(*(const uint2*)(xlr + (size_t)node * 256 + 128 + lane * 2));
    float4 r1 = h2f4(*(const uint2*)(xlr + (size_t)node * 256 + 192 + lane * 2));
    float4 a0 = ((const float4*)att)[lane];
    float4 a1 = ((const float4*)att)[32 + lane];

    float mA0 = -1e30f, mA1 = -1e30f, dA0 = 0.f, dA1 = 0.f;
    float mB0 = -1e30f, mB1 = -1e30f, dB0 = 0.f, dB1 = 0.f;
    float4 aA0 = make_float4(0.f,0.f,0.f,0.f), aA1 = make_float4(0.f,0.f,0.f,0.f);
    float4 aB0 = make_float4(0.f,0.f,0.f,0.f), aB1 = make_float4(0.f,0.f,0.f,0.f);

    int beg = g_off[node], end = g_off[node + 1];

    auto process = [&](int s, float& m0, float& m1, float& d0, float& d1,
                       float4& acc0, float4& acc1) {
        float4 l0 = h2f4(*(const uint2*)(xlr + (size_t)s * 256 + lane * 2));
        float4 l1 = h2f4(*(const uint2*)(xlr + (size_t)s * 256 + 64 + lane * 2));
        float4 e0, e1;
        e0.x = l0.x + r0.x; e0.x = e0.x > 0.f ? e0.x : 0.2f * e0.x;
        e0.y = l0.y + r0.y; e0.y = e0.y > 0.f ? e0.y : 0.2f * e0.y;
        e0.z = l0.z + r0.z; e0.z = e0.z > 0.f ? e0.z : 0.2f * e0.z;
        e0.w = l0.w + r0.w; e0.w = e0.w > 0.f ? e0.w : 0.2f * e0.w;
        e1.x = l1.x + r1.x; e1.x = e1.x > 0.f ? e1.x : 0.2f * e1.x;
        e1.y = l1.y + r1.y; e1.y = e1.y > 0.f ? e1.y : 0.2f * e1.y;
        e1.z = l1.z + r1.z; e1.z = e1.z > 0.f ? e1.z : 0.2f * e1.z;
        e1.w = l1.w + r1.w; e1.w = e1.w > 0.f ? e1.w : 0.2f * e1.w;
        float p0 = e0.x * a0.x + e0.y * a0.y + e0.z * a0.z + e0.w * a0.w;
        float p1 = e1.x * a1.x + e1.y * a1.y + e1.z * a1.z + e1.w * a1.w;
        #pragma unroll
        for (int o = 16; o; o >>= 1) {
            p0 += __shfl_xor_sync(0xffffffffu, p0, o);
            p1 += __shfl_xor_sync(0xffffffffu, p1, o);
        }
        float nm0 = fmaxf(m0, p0);
        float f0 = __expf(m0 - nm0);
        float w0 = __expf(p0 - nm0);
        m0 = nm0;
        d0 = d0 * f0 + w0;
        acc0.x = acc0.x * f0 + w0 * l0.x;
        acc0.y = acc0.y * f0 + w0 * l0.y;
        acc0.z = acc0.z * f0 + w0 * l0.z;
        acc0.w = acc0.w * f0 + w0 * l0.w;
        float nm1 = fmaxf(m1, p1);
        float f1 = __expf(m1 - nm1);
        float w1 = __expf(p1 - nm1);
        m1 = nm1;
        d1 = d1 * f1 + w1;
        acc1.x = acc1.x * f1 + w1 * l1.x;
        acc1.y = acc1.y * f1 + w1 * l1.y;
        acc1.z = acc1.z * f1 + w1 * l1.z;
        acc1.w = acc1.w * f1 + w1 * l1.w;
    };

    int i = beg;
    for (; i + 1 < end; i += 2) {
        int sA = g_esrc[i];
        int sB = g_esrc[i + 1];
        process(sA, mA0, mA1, dA0, dA1, aA0, aA1);
        process(sB, mB0, mB1, dB0, dB1, aB0, aB1);
    }
    if (i < end) process(g_esrc[i], mA0, mA1, dA0, dA1, aA0, aA1);

    {
        float m = fmaxf(mA0, mB0);
        float fA = __expf(mA0 - m), fB = __expf(mB0 - m);
        dA0 = dA0 * fA + dB0 * fB;
        aA0.x = aA0.x * fA + aB0.x * fB;
        aA0.y = aA0.y * fA + aB0.y * fB;
        aA0.z = aA0.z * fA + aB0.z * fB;
        aA0.w = aA0.w * fA + aB0.w * fB;
        m = fmaxf(mA1, mB1);
        fA = __expf(mA1 - m); fB = __expf(mB1 - m);
        dA1 = dA1 * fA + dB1 * fB;
        aA1.x = aA1.x * fA + aB1.x * fB;
        aA1.y = aA1.y * fA + aB1.y * fB;
        aA1.z = aA1.z * fA + aB1.z * fB;
        aA1.w = aA1.w * fA + aB1.w * fB;
    }

    float inv0 = 1.0f / (dA0 + 1e-16f);
    float inv1 = 1.0f / (dA1 + 1e-16f);
    const float4* gb4 = (const float4*)gat_b;
    float4 b0 = gb4[lane];
    float4 b1 = gb4[32 + lane];
    float o0 = aA0.x * inv0 + b0.x, o1 = aA0.y * inv0 + b0.y;
    float o2 = aA0.z * inv0 + b0.z, o3 = aA0.w * inv0 + b0.w;
    float o4 = aA1.x * inv1 + b1.x, o5 = aA1.y * inv1 + b1.y;
    float o6 = aA1.z * inv1 + b1.z, o7 = aA1.w * inv1 + b1.w;

    uint32_t h0, l0w, h1, l1w, h2, l2w, h3, l3w;
    split_pack(o0, o1, h0, l0w);
    split_pack(o2, o3, h1, l1w);
    split_pack(o4, o5, h2, l2w);
    split_pack(o6, o7, h3, l3w);
    size_t rb = (size_t)node * 128;
    gohi[rb + lane * 2]          = h0;  golo[rb + lane * 2]          = l0w;
    gohi[rb + lane * 2 + 1]      = h1;  golo[rb + lane * 2 + 1]      = l1w;
    gohi[rb + 64 + lane * 2]     = h2;  golo[rb + 64 + lane * 2]     = l2w;
    gohi[rb + 64 + lane * 2 + 1] = h3;  golo[rb + 64 + lane * 2 + 1] = l3w;
}

// ------------------------- launch --------------------------------------------
extern "C" void kernel_launch(void* const* d_in, const int* in_sizes, int n_in,
                              void* d_out, int out_size) {
    const float* x_in   = (const float*)d_in[0];
    const void*  edges  = d_in[1];
    const float* ln1_g  = (const float*)d_in[2];
    const float* ln1_b  = (const float*)d_in[3];
    const float* Wl     = (const float*)d_in[4];
    const float* bl     = (const float*)d_in[5];
    const float* Wr     = (const float*)d_in[6];
    const float* br     = (const float*)d_in[7];
    const float* att    = (const float*)d_in[8];
    const float* gat_b  = (const float*)d_in[9];
    const float* projW  = (const float*)d_in[10];
    const float* projb  = (const float*)d_in[11];
    const float* ln2_g  = (const float*)d_in[12];
    const float* ln2_b  = (const float*)d_in[13];
    const float* W1     = (const float*)d_in[14];
    const float* b1     = (const float*)d_in[15];
    const float* W2     = (const float*)d_in[16];
    const float* b2     = (const float*)d_in[17];

    const int N = in_sizes[0] / DIM;
    const int E = in_sizes[1] / 2;
    float* x = (float*)d_out;

    cudaFuncSetAttribute(gemm_kernel<1>, cudaFuncAttributeMaxDynamicSharedMemorySize, GEMM_SMEM);
    cudaFuncSetAttribute(gemm_kernel<2>, cudaFuncAttributeMaxDynamicSharedMemorySize, GEMM_SMEM);
    cudaFuncSetAttribute(gemm_kernel<3>, cudaFuncAttributeMaxDynamicSharedMemorySize, GEMM_SMEM3);
    cudaFuncSetAttribute(gemm_kernel<4>, cudaFuncAttributeMaxDynamicSharedMemorySize, GEMM_SMEM);

    void *p_xlr, *p_hhi, *p_hlo, *p_gohi, *p_golo, *p_mhi, *p_mlo, *p_wb, *p_blr;
    cudaGetSymbolAddress(&p_xlr, g_xlr);
    cudaGetSymbolAddress(&p_hhi, g_h_hi);
    cudaGetSymbolAddress(&p_hlo, g_h_lo);
    cudaGetSymbolAddress(&p_gohi, g_go_hi);
    cudaGetSymbolAddress(&p_golo, g_go_lo);
    cudaGetSymbolAddress(&p_mhi, g_mid_hi);
    cudaGetSymbolAddress(&p_mlo, g_mid_lo);
    cudaGetSymbolAddress(&p_wb, g_wb);
    cudaGetSymbolAddress(&p_blr, g_blr);
    uint32_t* xlr = (uint32_t*)p_xlr;
    uint32_t* hhi = (uint32_t*)p_hhi;
    uint32_t* hlo = (uint32_t*)p_hlo;
    uint32_t* gohi = (uint32_t*)p_gohi;
    uint32_t* golo = (uint32_t*)p_golo;
    uint32_t* mhi = (uint32_t*)p_mhi;
    uint32_t* mlo = (uint32_t*)p_mlo;
    uint32_t* wb = (uint32_t*)p_wb;
    float* blr = (float*)p_blr;

    cudaMemcpyAsync(x, x_in, (size_t)N * DIM * sizeof(float), cudaMemcpyDeviceToDevice);

    const int nb = (N + 1023) / 1024;
    detect_kernel<<<1, 256>>>(edges, E, N);
    clear_deg_kernel<<<(N + 255) / 256, 256>>>(N);
    decode_hist_kernel<<<(E + 255) / 256, 256>>>(edges, E);
    scanA_kernel<<<nb, 1024>>>(N);
    scanB_kernel<<<1, 32>>>(nb);
    scanC_kernel<<<(N + 255) / 256, 256>>>(N);
    scatter_kernel<<<(E + 255) / 256, 256>>>(E);

    wconv_all_kernel<<<(2 * LWORDS + 255) / 256, 256>>>(Wl, Wr, projW, W1, W2);
    bconcat_kernel<<<4, 256>>>(bl, br);

    const int ln_blocks = (N + 7) / 8;
    const int mtiles = (N + 127) / 128;

    ln_kernel<<<ln_blocks, 256>>>(x, ln1_g, ln1_b, hhi, hlo, N);

    for (int l = 0; l < 2; l++) {
        size_t off = (size_t)l * LWORDS;
        const uint32_t* wlr = wb + off;
        const uint32_t* pj  = wb + off + 32768;
        const uint32_t* w1  = wb + off + 49152;
        const uint32_t* w2  = wb + off + 81920;
        const float* at_l = att + (size_t)l * HD;
        const float* gb_l = gat_b + (size_t)l * HD;
        const float* pb_l = projb + (size_t)l * DIM;
        const float* b1_l = b1 + (size_t)l * MLPD;
        const float* b2_l = b2 + (size_t)l * DIM;

        // xlr = h @ [Wl|Wr] + blr  -> packed half2
        gemm_kernel<4><<<dim3(4, mtiles), 256, GEMM_SMEM>>>(
            hhi, hlo, wlr, blr + (size_t)l * 512, nullptr, xlr, nullptr,
            nullptr, nullptr, N, DIM, 512);
        gat_node_kernel<<<(N + 7) / 8, 256>>>(xlr, at_l, gb_l, gohi, golo, N);
        gemm_kernel<3><<<dim3(1, mtiles), 256, GEMM_SMEM3>>>(
            gohi, golo, pj, pb_l, x, hhi, hlo,
            ln2_g + (size_t)l * DIM, ln2_b + (size_t)l * DIM, N, HD, DIM);
        gemm_kernel<2><<<dim3(4, mtiles), 256, GEMM_SMEM>>>(
            hhi, hlo, w1, b1_l, nullptr, mhi, mlo,
            nullptr, nullptr, N, DIM, MLPD);
        if (l == 0) {
            gemm_kernel<3><<<dim3(1, mtiles), 256, GEMM_SMEM3>>>(
                mhi, mlo, w2, b2_l, x, hhi, hlo,
                ln1_g + DIM, ln1_b + DIM, N, MLPD, DIM);
        } else {
            gemm_kernel<1><<<dim3(1, mtiles), 256, GEMM_SMEM>>>(
                mhi, mlo, w2, b2_l, x, nullptr, nullptr,
                nullptr, nullptr, N, MLPD, DIM);
        }
    }
}

// round 11
// speedup vs baseline: 1.0287x; 1.0287x over previous
#include <cuda_runtime.h>
#include <cuda_fp16.h>
#include <math.h>
#include <stdint.h>

// ----------------------------------------------------------------------------
// GATv2 Transformer. GEMMs: fp16 mma.sync, A split hi+lo (2-term compensation),
// weights single fp16, cp.async double buffer, LN fused into N=128 epilogues.
// Edge phase: CSR-by-dst + dual-state online-softmax gather (fp32 xlr).
// GELU via sigmoid identity (1 MUFU instead of software tanhf).
// ----------------------------------------------------------------------------

#define MAXN 50000
#define MAXE 800000
#define DIM 128
#define HD 256
#define MLPD 512
#define LWORDS 114688

// ------------------------- scratch (device globals) -------------------------
__device__ __align__(256) float    g_xlr [(size_t)MAXN * 512];
__device__ __align__(256) uint32_t g_h_hi [(size_t)MAXN * (DIM/2)];
__device__ __align__(256) uint32_t g_h_lo [(size_t)MAXN * (DIM/2)];
__device__ __align__(256) uint32_t g_go_hi[(size_t)MAXN * (HD/2)];
__device__ __align__(256) uint32_t g_go_lo[(size_t)MAXN * (HD/2)];
__device__ __align__(256) uint32_t g_mid_hi[(size_t)MAXN * (MLPD/2)];
__device__ __align__(256) uint32_t g_mid_lo[(size_t)MAXN * (MLPD/2)];
__device__ __align__(256) uint32_t g_wb[2 * LWORDS];      // weights, single fp16
__device__ __align__(256) float    g_blr[2 * 512];
// CSR
__device__ __align__(256) int g_src[MAXE];
__device__ __align__(256) int g_dst[MAXE];
__device__ __align__(256) int g_esrc[MAXE];
__device__ __align__(256) int g_deg[MAXN];
__device__ __align__(256) int g_off[MAXN + 1];
__device__ __align__(256) int g_pos[MAXN];
__device__ __align__(256) int g_bsum[64];
__device__ __align__(256) int g_boff[64];
__device__ int g_is64;

// ------------------------- helpers -------------------------
__device__ __forceinline__ void split_pack(float x, float y, uint32_t& hi, uint32_t& lo) {
    __half hx = __float2half_rn(x);
    __half hy = __float2half_rn(y);
    __half lx = __float2half_rn(x - __half2float(hx));
    __half ly = __float2half_rn(y - __half2float(hy));
    hi = ((uint32_t)__half_as_ushort(hy) << 16) | (uint32_t)__half_as_ushort(hx);
    lo = ((uint32_t)__half_as_ushort(ly) << 16) | (uint32_t)__half_as_ushort(lx);
}
__device__ __forceinline__ uint32_t pack_h(float x, float y) {
    return ((uint32_t)__half_as_ushort(__float2half_rn(y)) << 16)
         | (uint32_t)__half_as_ushort(__float2half_rn(x));
}
// gelu(u) = 0.5u(1+tanh(z)) = u * sigmoid(2z), z = 0.79788456(u + 0.044715u^3)
__device__ __forceinline__ float fast_gelu(float u) {
    float z2 = 1.5957691216057308f * (u + 0.044715f * u * u * u);  // 2z
    return u * __fdividef(1.0f, 1.0f + __expf(-z2));
}

// ------------------------- edge dtype detect / decode+hist -------------------
__global__ void detect_kernel(const void* edges, int E, int N) {
    __shared__ int bad;
    if (threadIdx.x == 0) bad = 0;
    __syncthreads();
    const long long* p = (const long long*)edges;
    int n = E < 2048 ? E : 2048;
    for (int i = threadIdx.x; i < n; i += blockDim.x) {
        long long v = p[i];
        if (v < 0 || v >= (long long)N) atomicOr(&bad, 1);
    }
    __syncthreads();
    if (threadIdx.x == 0) g_is64 = bad ? 0 : 1;
}

__global__ void clear_deg_kernel(int N) {
    int i = blockIdx.x * blockDim.x + threadIdx.x;
    if (i < N) g_deg[i] = 0;
}

__global__ void decode_hist_kernel(const void* edges, int E) {
    int i = blockIdx.x * blockDim.x + threadIdx.x;
    if (i >= E) return;
    int s, d;
    if (g_is64) {
        const long long* p = (const long long*)edges;
        s = (int)p[i];
        d = (int)p[(size_t)E + i];
    } else {
        const int* p = (const int*)edges;
        s = p[i];
        d = p[(size_t)E + i];
    }
    g_src[i] = s;
    g_dst[i] = d;
    atomicAdd(&g_deg[d], 1);
}

// ---- 3-phase parallel scan ----
__global__ void scanA_kernel(int N) {
    int t = threadIdx.x;
    int i = blockIdx.x * 1024 + t;
    int lane = t & 31, w = t >> 5;
    int v = (i < N) ? g_deg[i] : 0;
    int s = v;
    #pragma unroll
    for (int o = 1; o < 32; o <<= 1) {
        int u = __shfl_up_sync(0xffffffffu, s, o);
        if (lane >= o) s += u;
    }
    __shared__ int wt[32];
    if (lane == 31) wt[w] = s;
    __syncthreads();
    if (w == 0) {
        int x = wt[lane];
        #pragma unroll
        for (int o = 1; o < 32; o <<= 1) {
            int u = __shfl_up_sync(0xffffffffu, x, o);
            if (lane >= o) x += u;
        }
        wt[lane] = x;
    }
    __syncthreads();
    if (w) s += wt[w - 1];
    if (i < N) g_off[i + 1] = s;
    if (t == 1023) g_bsum[blockIdx.x] = s;
}

__global__ void scanB_kernel(int nb) {
    int lane = threadIdx.x;
    int v0 = (lane < nb) ? g_bsum[lane] : 0;
    int v1 = (32 + lane < nb) ? g_bsum[32 + lane] : 0;
    int s0 = v0;
    #pragma unroll
    for (int o = 1; o < 32; o <<= 1) {
        int u = __shfl_up_sync(0xffffffffu, s0, o);
        if (lane >= o) s0 += u;
    }
    int tot0 = __shfl_sync(0xffffffffu, s0, 31);
    int s1 = v1;
    #pragma unroll
    for (int o = 1; o < 32; o <<= 1) {
        int u = __shfl_up_sync(0xffffffffu, s1, o);
        if (lane >= o) s1 += u;
    }
    if (lane < nb) g_boff[lane] = s0 - v0;
    if (32 + lane < nb) g_boff[32 + lane] = tot0 + s1 - v1;
}

__global__ void scanC_kernel(int N) {
    int i = blockIdx.x * blockDim.x + threadIdx.x;
    if (i == 0) g_off[0] = 0;
    if (i >= N) return;
    int b = i >> 10;
    int inc = g_off[i + 1] + g_boff[b];
    g_off[i + 1] = inc;
    g_pos[i] = inc - g_deg[i];
}

__global__ void scatter_kernel(int E) {
    int i = blockIdx.x * blockDim.x + threadIdx.x;
    if (i >= E) return;
    int p = atomicAdd(&g_pos[g_dst[i]], 1);
    g_esrc[p] = g_src[i];
}

// ---------------- fused weight convert (single fp16) -------------------------
__global__ void wconv_all_kernel(const float* __restrict__ Wl, const float* __restrict__ Wr,
                                 const float* __restrict__ pj, const float* __restrict__ W1,
                                 const float* __restrict__ W2) {
    int idx = blockIdx.x * blockDim.x + threadIdx.x;
    if (idx >= 2 * LWORDS) return;
    int layer = idx / LWORDS;
    int r = idx - layer * LWORDS;
    const float* W; int K, N;
    if (r < 16384)      { W = Wl + (size_t)layer * 32768; K = 128; N = 256; }
    else if (r < 32768) { W = Wr + (size_t)layer * 32768; r -= 16384; K = 128; N = 256; }
    else if (r < 49152) { W = pj + (size_t)layer * 32768; r -= 32768; K = 256; N = 128; }
    else if (r < 81920) { W = W1 + (size_t)layer * 65536; r -= 49152; K = 128; N = 512; }
    else                { W = W2 + (size_t)layer * 65536; r -= 81920; K = 512; N = 128; }
    int kw = K >> 1;
    int n = r / kw, kp = r - n * kw;
    float x = W[(size_t)(2 * kp) * N + n];
    float y = W[(size_t)(2 * kp + 1) * N + n];
    g_wb[idx] = pack_h(x, y);
}

__global__ void bconcat_kernel(const float* __restrict__ bl, const float* __restrict__ br) {
    int i = threadIdx.x + blockIdx.x * blockDim.x;
    if (i >= 1024) return;
    int layer = i >> 9, j = i & 511;
    float v = (j < 256) ? bl[layer * HD + j] : br[layer * HD + j - 256];
    g_blr[layer * 512 + j] = v;
}

// ------------------------- standalone layernorm ------------------------------
__global__ void ln_kernel(const float* __restrict__ x, const float* __restrict__ g,
                          const float* __restrict__ b,
                          uint32_t* __restrict__ ohi, uint32_t* __restrict__ olo, int N) {
    int row = (blockIdx.x * blockDim.x + threadIdx.x) >> 5;
    int lane = threadIdx.x & 31;
    if (row >= N) return;
    const float4* xr = (const float4*)x + (size_t)row * 32;
    float4 v = xr[lane];
    float s  = v.x + v.y + v.z + v.w;
    float sq = v.x*v.x + v.y*v.y + v.z*v.z + v.w*v.w;
    #pragma unroll
    for (int o = 16; o; o >>= 1) {
        s  += __shfl_xor_sync(0xffffffffu, s,  o);
        sq += __shfl_xor_sync(0xffffffffu, sq, o);
    }
    float m   = s * (1.0f / 128.0f);
    float var = sq * (1.0f / 128.0f) - m * m;
    float inv = rsqrtf(var + 1e-5f);
    float4 gg = ((const float4*)g)[lane];
    float4 bb = ((const float4*)b)[lane];
    float o0 = (v.x - m) * inv * gg.x + bb.x;
    float o1 = (v.y - m) * inv * gg.y + bb.y;
    float o2 = (v.z - m) * inv * gg.z + bb.z;
    float o3 = (v.w - m) * inv * gg.w + bb.w;
    uint32_t h0, l0, h1, l1;
    split_pack(o0, o1, h0, l0);
    split_pack(o2, o3, h1, l1);
    size_t base = (size_t)row * 64 + lane * 2;
    ohi[base] = h0; ohi[base + 1] = h1;
    olo[base] = l0; olo[base + 1] = l1;
}

// ------------------------- tensor-core GEMM --------------------------------
__device__ __forceinline__ void mma16816(float* c, const uint32_t* a, const uint32_t* b) {
    asm volatile(
        "mma.sync.aligned.m16n8k16.row.col.f32.f16.f16.f32 "
        "{%0,%1,%2,%3}, {%4,%5,%6,%7}, {%8,%9}, {%0,%1,%2,%3};"
        : "+f"(c[0]), "+f"(c[1]), "+f"(c[2]), "+f"(c[3])
        : "r"(a[0]), "r"(a[1]), "r"(a[2]), "r"(a[3]), "r"(b[0]), "r"(b[1]));
}

__device__ __forceinline__ void cpa16(uint32_t dst, const void* src, int bytes) {
    asm volatile("cp.async.cg.shared.global [%0], [%1], 16, %2;\n"
                 :: "r"(dst), "l"(src), "r"(bytes));
}

__device__ __forceinline__ int swz(int row, int kp) {
    return (row << 4) | (((kp >> 2) ^ ((row >> 1) & 3)) << 2) | (kp & 3);
}

#define TILE_WORDS 2048
#define BUF_WORDS  (3 * TILE_WORDS)          // Ah, Al, Bh
#define GEMM_SMEM  (2 * BUF_WORDS * 4)       // 48 KB
#define GEMM_SMEM3 65536                     // MODE 3 rowbuf

// MODE 0: store fp32; 1: accumulate fp32; 2: GELU then split hi/lo;
// MODE 3: accumulate fp32 + fused LayerNorm -> writes x (C) and split h (N==128)
template<int MODE>
__global__ __launch_bounds__(256, 2)
void gemm_kernel(const uint32_t* __restrict__ Ahi, const uint32_t* __restrict__ Alo,
                 const uint32_t* __restrict__ Bh_g,
                 const float* __restrict__ bias, float* __restrict__ C,
                 uint32_t* __restrict__ Chi, uint32_t* __restrict__ Clo,
                 const float* __restrict__ lng, const float* __restrict__ lnb,
                 int M, int K, int N) {
    extern __shared__ uint32_t sm[];

    const int tid  = threadIdx.x;
    const int lane = tid & 31;
    const int wid  = tid >> 5;
    const int warp_m = wid & 3;
    const int warp_n = wid >> 2;
    const int m0 = blockIdx.y * 128, n0 = blockIdx.x * 128;
    const int g  = lane >> 2;
    const int tg = lane & 3;
    const int kw = K >> 1;
    const int nk = K >> 5;

    const uint32_t sbase = (uint32_t)__cvta_generic_to_shared(sm);

    float acc[2][8][4];
    #pragma unroll
    for (int i = 0; i < 2; i++)
        #pragma unroll
        for (int j = 0; j < 8; j++)
            #pragma unroll
            for (int r = 0; r < 4; r++) acc[i][j][r] = 0.0f;

    auto issue = [&](int kt, int b) {
        uint32_t bufb = sbase + (uint32_t)(b * BUF_WORDS) * 4;
        #pragma unroll
        for (int t = 0; t < 2; t++) {
            int chunk = tid + t * 256;
            int row = chunk >> 2, c = chunk & 3;
            int dstw = (row << 4) | ((c ^ ((row >> 1) & 3)) << 2);
            int asz = (m0 + row < M) ? 16 : 0;
            const uint32_t* asrc = Ahi + (size_t)(m0 + row) * kw + kt * 16 + c * 4;
            const uint32_t* alsr = Alo + (size_t)(m0 + row) * kw + kt * 16 + c * 4;
            const uint32_t* bsrc = Bh_g + (size_t)(n0 + row) * kw + kt * 16 + c * 4;
            cpa16(bufb + (uint32_t)dstw * 4,                    asrc, asz);
            cpa16(bufb + (uint32_t)(TILE_WORDS + dstw) * 4,     alsr, asz);
            cpa16(bufb + (uint32_t)(2 * TILE_WORDS + dstw) * 4, bsrc, 16);
        }
        asm volatile("cp.async.commit_group;\n");
    };

    issue(0, 0);

    for (int kt = 0; kt < nk; kt++) {
        const bool more = (kt + 1 < nk);
        if (more) issue(kt + 1, (kt + 1) & 1);
        if (more) { asm volatile("cp.async.wait_group 1;\n"); }
        else      { asm volatile("cp.async.wait_group 0;\n"); }
        __syncthreads();

        const uint32_t* Ah = sm + (kt & 1) * BUF_WORDS;
        const uint32_t* Al = Ah + TILE_WORDS;
        const uint32_t* Bh = Ah + 2 * TILE_WORDS;
        #pragma unroll
        for (int ks = 0; ks < 2; ks++) {
            const int kb = ks * 4;
            uint32_t ah[2][4], al[2][4];
            #pragma unroll
            for (int mt = 0; mt < 2; mt++) {
                int r0 = warp_m * 32 + mt * 16;
                ah[mt][0] = Ah[swz(r0 + g,     kb + tg)];
                ah[mt][1] = Ah[swz(r0 + g + 8, kb + tg)];
                ah[mt][2] = Ah[swz(r0 + g,     kb + tg + 8)];
                ah[mt][3] = Ah[swz(r0 + g + 8, kb + tg + 8)];
                al[mt][0] = Al[swz(r0 + g,     kb + tg)];
                al[mt][1] = Al[swz(r0 + g + 8, kb + tg)];
                al[mt][2] = Al[swz(r0 + g,     kb + tg + 8)];
                al[mt][3] = Al[swz(r0 + g + 8, kb + tg + 8)];
            }
            #pragma unroll
            for (int nt = 0; nt < 8; nt++) {
                int col = warp_n * 64 + nt * 8 + g;
                uint32_t bh[2];
                bh[0] = Bh[swz(col, kb + tg)];
                bh[1] = Bh[swz(col, kb + tg + 8)];
                #pragma unroll
                for (int mt = 0; mt < 2; mt++) {
                    float* c = acc[mt][nt];
                    mma16816(c, ah[mt], bh);
                    mma16816(c, al[mt], bh);
                }
            }
        }
        __syncthreads();
    }

    // ---- epilogue ----
    float* rowbuf = (float*)sm;   // MODE 3: 128x128 staging
    #pragma unroll
    for (int mt = 0; mt < 2; mt++) {
        int rloc = warp_m * 32 + mt * 16 + (lane >> 2);
        int row = m0 + rloc;
        #pragma unroll
        for (int nt = 0; nt < 8; nt++) {
            int col = n0 + warp_n * 64 + nt * 8 + (lane & 3) * 2;
            float2 bb = *(const float2*)(bias + col);
            #pragma unroll
            for (int half = 0; half < 2; half++) {
                int r = row + half * 8;
                if (r >= M) continue;
                float v0 = acc[mt][nt][2 * half]     + bb.x;
                float v1 = acc[mt][nt][2 * half + 1] + bb.y;
                if (MODE == 2) {
                    v0 = fast_gelu(v0);
                    v1 = fast_gelu(v1);
                    uint32_t h, l;
                    split_pack(v0, v1, h, l);
                    size_t w = (size_t)r * (N >> 1) + (col >> 1);
                    Chi[w] = h; Clo[w] = l;
                } else if (MODE == 3) {
                    float2 old = *(float2*)(C + (size_t)r * N + col);
                    rowbuf[(rloc + half * 8) * 128 + (col - n0)]     = v0 + old.x;
                    rowbuf[(rloc + half * 8) * 128 + (col - n0) + 1] = v1 + old.y;
                } else {
                    float2* dst = (float2*)(C + (size_t)r * N + col);
                    if (MODE == 1) {
                        float2 old = *dst;
                        v0 += old.x; v1 += old.y;
                    }
                    *dst = make_float2(v0, v1);
                }
            }
        }
    }

    if (MODE == 3) {
        __syncthreads();
        float4 gg = ((const float4*)lng)[lane];
        float4 bb2 = ((const float4*)lnb)[lane];
        for (int rr = wid * 16; rr < wid * 16 + 16; rr++) {
            int r = m0 + rr;
            if (r >= M) break;
            float4 v = ((const float4*)(rowbuf + rr * 128))[lane];
            float s  = v.x + v.y + v.z + v.w;
            float sq = v.x*v.x + v.y*v.y + v.z*v.z + v.w*v.w;
            #pragma unroll
            for (int o = 16; o; o >>= 1) {
                s  += __shfl_xor_sync(0xffffffffu, s,  o);
                sq += __shfl_xor_sync(0xffffffffu, sq, o);
            }
            float m   = s * (1.0f / 128.0f);
            float var = sq * (1.0f / 128.0f) - m * m;
            float inv = rsqrtf(var + 1e-5f);
            ((float4*)(C + (size_t)r * 128))[lane] = v;
            float o0 = (v.x - m) * inv * gg.x + bb2.x;
            float o1 = (v.y - m) * inv * gg.y + bb2.y;
            float o2 = (v.z - m) * inv * gg.z + bb2.z;
            float o3 = (v.w - m) * inv * gg.w + bb2.w;
            uint32_t h0, l0, h1, l1;
            split_pack(o0, o1, h0, l0);
            split_pack(o2, o3, h1, l1);
            size_t base = (size_t)r * 64 + lane * 2;
            Chi[base] = h0; Chi[base + 1] = h1;
            Clo[base] = l0; Clo[base + 1] = l1;
        }
    }
}

// ------------------- fused GATv2 node kernel (warp per dst) ------------------
__global__ void gat_node_kernel(const float* __restrict__ xlr,
                                const float* __restrict__ att,
                                const float* __restrict__ gat_b,
                                uint32_t* __restrict__ gohi, uint32_t* __restrict__ golo,
                                int N) {
    int node = (blockIdx.x * blockDim.x + threadIdx.x) >> 5;
    int lane = threadIdx.x & 31;
    if (node >= N) return;

    const float4* base = (const float4*)xlr;
    float4 r0 = base[(size_t)node * 128 + 64 + lane];
    float4 r1 = base[(size_t)node * 128 + 96 + lane];
    float4 a0 = ((const float4*)att)[lane];
    float4 a1 = ((const float4*)att)[32 + lane];

    float mA0 = -1e30f, mA1 = -1e30f, dA0 = 0.f, dA1 = 0.f;
    float mB0 = -1e30f, mB1 = -1e30f, dB0 = 0.f, dB1 = 0.f;
    float4 aA0 = make_float4(0.f,0.f,0.f,0.f), aA1 = make_float4(0.f,0.f,0.f,0.f);
    float4 aB0 = make_float4(0.f,0.f,0.f,0.f), aB1 = make_float4(0.f,0.f,0.f,0.f);

    int beg = g_off[node], end = g_off[node + 1];

    auto process = [&](int s, float& m0, float& m1, float& d0, float& d1,
                       float4& acc0, float4& acc1) {
        float4 l0 = base[(size_t)s * 128 + lane];
        float4 l1 = base[(size_t)s * 128 + 32 + lane];
        float4 e0, e1;
        e0.x = l0.x + r0.x; e0.x = e0.x > 0.f ? e0.x : 0.2f * e0.x;
        e0.y = l0.y + r0.y; e0.y = e0.y > 0.f ? e0.y : 0.2f * e0.y;
        e0.z = l0.z + r0.z; e0.z = e0.z > 0.f ? e0.z : 0.2f * e0.z;
        e0.w = l0.w + r0.w; e0.w = e0.w > 0.f ? e0.w : 0.2f * e0.w;
        e1.x = l1.x + r1.x; e1.x = e1.x > 0.f ? e1.x : 0.2f * e1.x;
        e1.y = l1.y + r1.y; e1.y = e1.y > 0.f ? e1.y : 0.2f * e1.y;
        e1.z = l1.z + r1.z; e1.z = e1.z > 0.f ? e1.z : 0.2f * e1.z;
        e1.w = l1.w + r1.w; e1.w = e1.w > 0.f ? e1.w : 0.2f * e1.w;
        float p0 = e0.x * a0.x + e0.y * a0.y + e0.z * a0.z + e0.w * a0.w;
        float p1 = e1.x * a1.x + e1.y * a1.y + e1.z * a1.z + e1.w * a1.w;
        #pragma unroll
        for (int o = 16; o; o >>= 1) {
            p0 += __shfl_xor_sync(0xffffffffu, p0, o);
            p1 += __shfl_xor_sync(0xffffffffu, p1, o);
        }
        float nm0 = fmaxf(m0, p0);
        float f0 = __expf(m0 - nm0);
        float w0 = __expf(p0 - nm0);
        m0 = nm0;
        d0 = d0 * f0 + w0;
        acc0.x = acc0.x * f0 + w0 * l0.x;
        acc0.y = acc0.y * f0 + w0 * l0.y;
        acc0.z = acc0.z * f0 + w0 * l0.z;
        acc0.w = acc0.w * f0 + w0 * l0.w;
        float nm1 = fmaxf(m1, p1);
        float f1 = __expf(m1 - nm1);
        float w1 = __expf(p1 - nm1);
        m1 = nm1;
        d1 = d1 * f1 + w1;
        acc1.x = acc1.x * f1 + w1 * l1.x;
        acc1.y = acc1.y * f1 + w1 * l1.y;
        acc1.z = acc1.z * f1 + w1 * l1.z;
        acc1.w = acc1.w * f1 + w1 * l1.w;
    };

    int i = beg;
    for (; i + 1 < end; i += 2) {
        int sA = g_esrc[i];
        int sB = g_esrc[i + 1];
        process(sA, mA0, mA1, dA0, dA1, aA0, aA1);
        process(sB, mB0, mB1, dB0, dB1, aB0, aB1);
    }
    if (i < end) process(g_esrc[i], mA0, mA1, dA0, dA1, aA0, aA1);

    {
        float m = fmaxf(mA0, mB0);
        float fA = __expf(mA0 - m), fB = __expf(mB0 - m);
        dA0 = dA0 * fA + dB0 * fB;
        aA0.x = aA0.x * fA + aB0.x * fB;
        aA0.y = aA0.y * fA + aB0.y * fB;
        aA0.z = aA0.z * fA + aB0.z * fB;
        aA0.w = aA0.w * fA + aB0.w * fB;
        m = fmaxf(mA1, mB1);
        fA = __expf(mA1 - m); fB = __expf(mB1 - m);
        dA1 = dA1 * fA + dB1 * fB;
        aA1.x = aA1.x * fA + aB1.x * fB;
        aA1.y = aA1.y * fA + aB1.y * fB;
        aA1.z = aA1.z * fA + aB1.z * fB;
        aA1.w = aA1.w * fA + aB1.w * fB;
    }

    float inv0 = 1.0f / (dA0 + 1e-16f);
    float inv1 = 1.0f / (dA1 + 1e-16f);
    const float4* gb4 = (const float4*)gat_b;
    float4 b0 = gb4[lane];
    float4 b1 = gb4[32 + lane];
    float o0 = aA0.x * inv0 + b0.x, o1 = aA0.y * inv0 + b0.y;
    float o2 = aA0.z * inv0 + b0.z, o3 = aA0.w * inv0 + b0.w;
    float o4 = aA1.x * inv1 + b1.x, o5 = aA1.y * inv1 + b1.y;
    float o6 = aA1.z * inv1 + b1.z, o7 = aA1.w * inv1 + b1.w;

    uint32_t h0, l0w, h1, l1w, h2, l2w, h3, l3w;
    split_pack(o0, o1, h0, l0w);
    split_pack(o2, o3, h1, l1w);
    split_pack(o4, o5, h2, l2w);
    split_pack(o6, o7, h3, l3w);
    size_t rb = (size_t)node * 128;
    gohi[rb + lane * 2]          = h0;  golo[rb + lane * 2]          = l0w;
    gohi[rb + lane * 2 + 1]      = h1;  golo[rb + lane * 2 + 1]      = l1w;
    gohi[rb + 64 + lane * 2]     = h2;  golo[rb + 64 + lane * 2]     = l2w;
    gohi[rb + 64 + lane * 2 + 1] = h3;  golo[rb + 64 + lane * 2 + 1] = l3w;
}

// ------------------------- launch --------------------------------------------
extern "C" void kernel_launch(void* const* d_in, const int* in_sizes, int n_in,
                              void* d_out, int out_size) {
    const float* x_in   = (const float*)d_in[0];
    const void*  edges  = d_in[1];
    const float* ln1_g  = (const float*)d_in[2];
    const float* ln1_b  = (const float*)d_in[3];
    const float* Wl     = (const float*)d_in[4];
    const float* bl     = (const float*)d_in[5];
    const float* Wr     = (const float*)d_in[6];
    const float* br     = (const float*)d_in[7];
    const float* att    = (const float*)d_in[8];
    const float* gat_b  = (const float*)d_in[9];
    const float* projW  = (const float*)d_in[10];
    const float* projb  = (const float*)d_in[11];
    const float* ln2_g  = (const float*)d_in[12];
    const float* ln2_b  = (const float*)d_in[13];
    const float* W1     = (const float*)d_in[14];
    const float* b1     = (const float*)d_in[15];
    const float* W2     = (const float*)d_in[16];
    const float* b2     = (const float*)d_in[17];

    const int N = in_sizes[0] / DIM;
    const int E = in_sizes[1] / 2;
    float* x = (float*)d_out;

    cudaFuncSetAttribute(gemm_kernel<0>, cudaFuncAttributeMaxDynamicSharedMemorySize, GEMM_SMEM);
    cudaFuncSetAttribute(gemm_kernel<1>, cudaFuncAttributeMaxDynamicSharedMemorySize, GEMM_SMEM);
    cudaFuncSetAttribute(gemm_kernel<2>, cudaFuncAttributeMaxDynamicSharedMemorySize, GEMM_SMEM);
    cudaFuncSetAttribute(gemm_kernel<3>, cudaFuncAttributeMaxDynamicSharedMemorySize, GEMM_SMEM3);

    void *p_xlr, *p_hhi, *p_hlo, *p_gohi, *p_golo, *p_mhi, *p_mlo, *p_wb, *p_blr;
    cudaGetSymbolAddress(&p_xlr, g_xlr);
    cudaGetSymbolAddress(&p_hhi, g_h_hi);
    cudaGetSymbolAddress(&p_hlo, g_h_lo);
    cudaGetSymbolAddress(&p_gohi, g_go_hi);
    cudaGetSymbolAddress(&p_golo, g_go_lo);
    cudaGetSymbolAddress(&p_mhi, g_mid_hi);
    cudaGetSymbolAddress(&p_mlo, g_mid_lo);
    cudaGetSymbolAddress(&p_wb, g_wb);
    cudaGetSymbolAddress(&p_blr, g_blr);
    float* xlr = (float*)p_xlr;
    uint32_t* hhi = (uint32_t*)p_hhi;
    uint32_t* hlo = (uint32_t*)p_hlo;
    uint32_t* gohi = (uint32_t*)p_gohi;
    uint32_t* golo = (uint32_t*)p_golo;
    uint32_t* mhi = (uint32_t*)p_mhi;
    uint32_t* mlo = (uint32_t*)p_mlo;
    uint32_t* wb = (uint32_t*)p_wb;
    float* blr = (float*)p_blr;

    cudaMemcpyAsync(x, x_in, (size_t)N * DIM * sizeof(float), cudaMemcpyDeviceToDevice);

    const int nb = (N + 1023) / 1024;
    detect_kernel<<<1, 256>>>(edges, E, N);
    clear_deg_kernel<<<(N + 255) / 256, 256>>>(N);
    decode_hist_kernel<<<(E + 255) / 256, 256>>>(edges, E);
    scanA_kernel<<<nb, 1024>>>(N);
    scanB_kernel<<<1, 32>>>(nb);
    scanC_kernel<<<(N + 255) / 256, 256>>>(N);
    scatter_kernel<<<(E + 255) / 256, 256>>>(E);

    wconv_all_kernel<<<(2 * LWORDS + 255) / 256, 256>>>(Wl, Wr, projW, W1, W2);
    bconcat_kernel<<<4, 256>>>(bl, br);

    const int ln_blocks = (N + 7) / 8;
    const int mtiles = (N + 127) / 128;

    ln_kernel<<<ln_blocks, 256>>>(x, ln1_g, ln1_b, hhi, hlo, N);

    for (int l = 0; l < 2; l++) {
        size_t off = (size_t)l * LWORDS;
        const uint32_t* wlr = wb + off;
        const uint32_t* pj  = wb + off + 32768;
        const uint32_t* w1  = wb + off + 49152;
        const uint32_t* w2  = wb + off + 81920;
        const float* at_l = att + (size_t)l * HD;
        const float* gb_l = gat_b + (size_t)l * HD;
        const float* pb_l = projb + (size_t)l * DIM;
        const float* b1_l = b1 + (size_t)l * MLPD;
        const float* b2_l = b2 + (size_t)l * DIM;

        gemm_kernel<0><<<dim3(4, mtiles), 256, GEMM_SMEM>>>(
            hhi, hlo, wlr, blr + (size_t)l * 512, xlr, nullptr, nullptr,
            nullptr, nullptr, N, DIM, 512);
        gat_node_kernel<<<(N + 7) / 8, 256>>>(xlr, at_l, gb_l, gohi, golo, N);
        gemm_kernel<3><<<dim3(1, mtiles), 256, GEMM_SMEM3>>>(
            gohi, golo, pj, pb_l, x, hhi, hlo,
            ln2_g + (size_t)l * DIM, ln2_b + (size_t)l * DIM, N, HD, DIM);
        gemm_kernel<2><<<dim3(4, mtiles), 256, GEMM_SMEM>>>(
            hhi, hlo, w1, b1_l, nullptr, mhi, mlo,
            nullptr, nullptr, N, DIM, MLPD);
        if (l == 0) {
            gemm_kernel<3><<<dim3(1, mtiles), 256, GEMM_SMEM3>>>(
                mhi, mlo, w2, b2_l, x, hhi, hlo,
                ln1_g + DIM, ln1_b + DIM, N, MLPD, DIM);
        } else {
            gemm_kernel<1><<<dim3(1, mtiles), 256, GEMM_SMEM>>>(
                mhi, mlo, w2, b2_l, x, nullptr, nullptr,
                nullptr, nullptr, N, MLPD, DIM);
        }
    }
}

// round 12
// speedup vs baseline: 1.0471x; 1.0179x over previous
#include <cuda_runtime.h>
#include <cuda_fp16.h>
#include <math.h>
#include <stdint.h>

// ----------------------------------------------------------------------------
// GATv2 Transformer. GEMMs: fp16 mma.sync, A split hi+lo, weights fp16,
// cp.async double buffer, persistent-CTA tiling (no wave quantization),
// LN fused into N=128 epilogues. Edge: CSR + dual-state online softmax.
// ----------------------------------------------------------------------------

#define MAXN 50000
#define MAXE 800000
#define DIM 128
#define HD 256
#define MLPD 512
#define LWORDS 114688
#define PERSIST_BLOCKS 296     // 148 SMs x 2 CTAs

// ------------------------- scratch (device globals) -------------------------
__device__ __align__(256) float    g_xlr [(size_t)MAXN * 512];
__device__ __align__(256) uint32_t g_h_hi [(size_t)MAXN * (DIM/2)];
__device__ __align__(256) uint32_t g_h_lo [(size_t)MAXN * (DIM/2)];
__device__ __align__(256) uint32_t g_go_hi[(size_t)MAXN * (HD/2)];
__device__ __align__(256) uint32_t g_go_lo[(size_t)MAXN * (HD/2)];
__device__ __align__(256) uint32_t g_mid_hi[(size_t)MAXN * (MLPD/2)];
__device__ __align__(256) uint32_t g_mid_lo[(size_t)MAXN * (MLPD/2)];
__device__ __align__(256) uint32_t g_wb[2 * LWORDS];
__device__ __align__(256) float    g_blr[2 * 512];
// CSR
__device__ __align__(256) int g_src[MAXE];
__device__ __align__(256) int g_dst[MAXE];
__device__ __align__(256) int g_esrc[MAXE];
__device__ __align__(256) int g_deg[MAXN];
__device__ __align__(256) int g_off[MAXN + 1];
__device__ __align__(256) int g_pos[MAXN];
__device__ __align__(256) int g_bsum[64];
__device__ __align__(256) int g_boff[64];
__device__ int g_is64;

// ------------------------- helpers -------------------------
__device__ __forceinline__ void split_pack(float x, float y, uint32_t& hi, uint32_t& lo) {
    __half hx = __float2half_rn(x);
    __half hy = __float2half_rn(y);
    __half lx = __float2half_rn(x - __half2float(hx));
    __half ly = __float2half_rn(y - __half2float(hy));
    hi = ((uint32_t)__half_as_ushort(hy) << 16) | (uint32_t)__half_as_ushort(hx);
    lo = ((uint32_t)__half_as_ushort(ly) << 16) | (uint32_t)__half_as_ushort(lx);
}
__device__ __forceinline__ uint32_t pack_h(float x, float y) {
    return ((uint32_t)__half_as_ushort(__float2half_rn(y)) << 16)
         | (uint32_t)__half_as_ushort(__float2half_rn(x));
}
__device__ __forceinline__ float fast_gelu(float u) {
    float z2 = 1.5957691216057308f * (u + 0.044715f * u * u * u);
    return u * __fdividef(1.0f, 1.0f + __expf(-z2));
}

// ------------------------- edge dtype detect / decode+hist -------------------
__global__ void detect_kernel(const void* edges, int E, int N) {
    __shared__ int bad;
    if (threadIdx.x == 0) bad = 0;
    __syncthreads();
    const long long* p = (const long long*)edges;
    int n = E < 2048 ? E : 2048;
    for (int i = threadIdx.x; i < n; i += blockDim.x) {
        long long v = p[i];
        if (v < 0 || v >= (long long)N) atomicOr(&bad, 1);
    }
    __syncthreads();
    if (threadIdx.x == 0) g_is64 = bad ? 0 : 1;
}

__global__ void clear_deg_kernel(int N) {
    int i = blockIdx.x * blockDim.x + threadIdx.x;
    if (i < N) g_deg[i] = 0;
}

__global__ void decode_hist_kernel(const void* edges, int E) {
    int i = blockIdx.x * blockDim.x + threadIdx.x;
    if (i >= E) return;
    int s, d;
    if (g_is64) {
        const long long* p = (const long long*)edges;
        s = (int)p[i];
        d = (int)p[(size_t)E + i];
    } else {
        const int* p = (const int*)edges;
        s = p[i];
        d = p[(size_t)E + i];
    }
    g_src[i] = s;
    g_dst[i] = d;
    atomicAdd(&g_deg[d], 1);
}

// ---- 3-phase parallel scan ----
__global__ void scanA_kernel(int N) {
    int t = threadIdx.x;
    int i = blockIdx.x * 1024 + t;
    int lane = t & 31, w = t >> 5;
    int v = (i < N) ? g_deg[i] : 0;
    int s = v;
    #pragma unroll
    for (int o = 1; o < 32; o <<= 1) {
        int u = __shfl_up_sync(0xffffffffu, s, o);
        if (lane >= o) s += u;
    }
    __shared__ int wt[32];
    if (lane == 31) wt[w] = s;
    __syncthreads();
    if (w == 0) {
        int x = wt[lane];
        #pragma unroll
        for (int o = 1; o < 32; o <<= 1) {
            int u = __shfl_up_sync(0xffffffffu, x, o);
            if (lane >= o) x += u;
        }
        wt[lane] = x;
    }
    __syncthreads();
    if (w) s += wt[w - 1];
    if (i < N) g_off[i + 1] = s;
    if (t == 1023) g_bsum[blockIdx.x] = s;
}

__global__ void scanB_kernel(int nb) {
    int lane = threadIdx.x;
    int v0 = (lane < nb) ? g_bsum[lane] : 0;
    int v1 = (32 + lane < nb) ? g_bsum[32 + lane] : 0;
    int s0 = v0;
    #pragma unroll
    for (int o = 1; o < 32; o <<= 1) {
        int u = __shfl_up_sync(0xffffffffu, s0, o);
        if (lane >= o) s0 += u;
    }
    int tot0 = __shfl_sync(0xffffffffu, s0, 31);
    int s1 = v1;
    #pragma unroll
    for (int o = 1; o < 32; o <<= 1) {
        int u = __shfl_up_sync(0xffffffffu, s1, o);
        if (lane >= o) s1 += u;
    }
    if (lane < nb) g_boff[lane] = s0 - v0;
    if (32 + lane < nb) g_boff[32 + lane] = tot0 + s1 - v1;
}

__global__ void scanC_kernel(int N) {
    int i = blockIdx.x * blockDim.x + threadIdx.x;
    if (i == 0) g_off[0] = 0;
    if (i >= N) return;
    int b = i >> 10;
    int inc = g_off[i + 1] + g_boff[b];
    g_off[i + 1] = inc;
    g_pos[i] = inc - g_deg[i];
}

__global__ void scatter_kernel(int E) {
    int i = blockIdx.x * blockDim.x + threadIdx.x;
    if (i >= E) return;
    int p = atomicAdd(&g_pos[g_dst[i]], 1);
    g_esrc[p] = g_src[i];
}

// ---------------- fused weight convert (single fp16) -------------------------
__global__ void wconv_all_kernel(const float* __restrict__ Wl, const float* __restrict__ Wr,
                                 const float* __restrict__ pj, const float* __restrict__ W1,
                                 const float* __restrict__ W2) {
    int idx = blockIdx.x * blockDim.x + threadIdx.x;
    if (idx >= 2 * LWORDS) return;
    int layer = idx / LWORDS;
    int r = idx - layer * LWORDS;
    const float* W; int K, N;
    if (r < 16384)      { W = Wl + (size_t)layer * 32768; K = 128; N = 256; }
    else if (r < 32768) { W = Wr + (size_t)layer * 32768; r -= 16384; K = 128; N = 256; }
    else if (r < 49152) { W = pj + (size_t)layer * 32768; r -= 32768; K = 256; N = 128; }
    else if (r < 81920) { W = W1 + (size_t)layer * 65536; r -= 49152; K = 128; N = 512; }
    else                { W = W2 + (size_t)layer * 65536; r -= 81920; K = 512; N = 128; }
    int kw = K >> 1;
    int n = r / kw, kp = r - n * kw;
    float x = W[(size_t)(2 * kp) * N + n];
    float y = W[(size_t)(2 * kp + 1) * N + n];
    g_wb[idx] = pack_h(x, y);
}

__global__ void bconcat_kernel(const float* __restrict__ bl, const float* __restrict__ br) {
    int i = threadIdx.x + blockIdx.x * blockDim.x;
    if (i >= 1024) return;
    int layer = i >> 9, j = i & 511;
    float v = (j < 256) ? bl[layer * HD + j] : br[layer * HD + j - 256];
    g_blr[layer * 512 + j] = v;
}

// ------------------------- standalone layernorm ------------------------------
__global__ void ln_kernel(const float* __restrict__ x, const float* __restrict__ g,
                          const float* __restrict__ b,
                          uint32_t* __restrict__ ohi, uint32_t* __restrict__ olo, int N) {
    int row = (blockIdx.x * blockDim.x + threadIdx.x) >> 5;
    int lane = threadIdx.x & 31;
    if (row >= N) return;
    const float4* xr = (const float4*)x + (size_t)row * 32;
    float4 v = xr[lane];
    float s  = v.x + v.y + v.z + v.w;
    float sq = v.x*v.x + v.y*v.y + v.z*v.z + v.w*v.w;
    #pragma unroll
    for (int o = 16; o; o >>= 1) {
        s  += __shfl_xor_sync(0xffffffffu, s,  o);
        sq += __shfl_xor_sync(0xffffffffu, sq, o);
    }
    float m   = s * (1.0f / 128.0f);
    float var = sq * (1.0f / 128.0f) - m * m;
    float inv = rsqrtf(var + 1e-5f);
    float4 gg = ((const float4*)g)[lane];
    float4 bb = ((const float4*)b)[lane];
    float o0 = (v.x - m) * inv * gg.x + bb.x;
    float o1 = (v.y - m) * inv * gg.y + bb.y;
    float o2 = (v.z - m) * inv * gg.z + bb.z;
    float o3 = (v.w - m) * inv * gg.w + bb.w;
    uint32_t h0, l0, h1, l1;
    split_pack(o0, o1, h0, l0);
    split_pack(o2, o3, h1, l1);
    size_t base = (size_t)row * 64 + lane * 2;
    ohi[base] = h0; ohi[base + 1] = h1;
    olo[base] = l0; olo[base + 1] = l1;
}

// ------------------------- tensor-core GEMM --------------------------------
__device__ __forceinline__ void mma16816(float* c, const uint32_t* a, const uint32_t* b) {
    asm volatile(
        "mma.sync.aligned.m16n8k16.row.col.f32.f16.f16.f32 "
        "{%0,%1,%2,%3}, {%4,%5,%6,%7}, {%8,%9}, {%0,%1,%2,%3};"
        : "+f"(c[0]), "+f"(c[1]), "+f"(c[2]), "+f"(c[3])
        : "r"(a[0]), "r"(a[1]), "r"(a[2]), "r"(a[3]), "r"(b[0]), "r"(b[1]));
}

__device__ __forceinline__ void cpa16(uint32_t dst, const void* src, int bytes) {
    asm volatile("cp.async.cg.shared.global [%0], [%1], 16, %2;\n"
                 :: "r"(dst), "l"(src), "r"(bytes));
}

__device__ __forceinline__ int swz(int row, int kp) {
    return (row << 4) | (((kp >> 2) ^ ((row >> 1) & 3)) << 2) | (kp & 3);
}

#define TILE_WORDS 2048
#define BUF_WORDS  (3 * TILE_WORDS)
#define GEMM_SMEM  (2 * BUF_WORDS * 4)       // 48 KB
#define GEMM_SMEM3 65536                     // MODE 3 rowbuf

// MODE 0: store fp32; 1: accumulate fp32; 2: GELU then split hi/lo;
// MODE 3: accumulate + fused LayerNorm -> writes x (C) and split h (N==128)
// Persistent: each block loops over output tiles with stride gridDim.x.
template<int MODE>
__global__ __launch_bounds__(256, 2)
void gemm_kernel(const uint32_t* __restrict__ Ahi, const uint32_t* __restrict__ Alo,
                 const uint32_t* __restrict__ Bh_g,
                 const float* __restrict__ bias, float* __restrict__ C,
                 uint32_t* __restrict__ Chi, uint32_t* __restrict__ Clo,
                 const float* __restrict__ lng, const float* __restrict__ lnb,
                 int M, int K, int N) {
    extern __shared__ uint32_t sm[];

    const int tid  = threadIdx.x;
    const int lane = tid & 31;
    const int wid  = tid >> 5;
    const int warp_m = wid & 3;
    const int warp_n = wid >> 2;
    const int g  = lane >> 2;
    const int tg = lane & 3;
    const int kw = K >> 1;
    const int nk = K >> 5;
    const int nx = N >> 7;
    const int ntiles = nx * ((M + 127) >> 7);

    const uint32_t sbase = (uint32_t)__cvta_generic_to_shared(sm);

    for (int tile = blockIdx.x; tile < ntiles; tile += gridDim.x) {
        const int n0 = (tile % nx) * 128;
        const int m0 = (tile / nx) * 128;

        float acc[2][8][4];
        #pragma unroll
        for (int i = 0; i < 2; i++)
            #pragma unroll
            for (int j = 0; j < 8; j++)
                #pragma unroll
                for (int r = 0; r < 4; r++) acc[i][j][r] = 0.0f;

        auto issue = [&](int kt, int b) {
            uint32_t bufb = sbase + (uint32_t)(b * BUF_WORDS) * 4;
            #pragma unroll
            for (int t = 0; t < 2; t++) {
                int chunk = tid + t * 256;
                int row = chunk >> 2, c = chunk & 3;
                int dstw = (row << 4) | ((c ^ ((row >> 1) & 3)) << 2);
                int asz = (m0 + row < M) ? 16 : 0;
                const uint32_t* asrc = Ahi + (size_t)(m0 + row) * kw + kt * 16 + c * 4;
                const uint32_t* alsr = Alo + (size_t)(m0 + row) * kw + kt * 16 + c * 4;
                const uint32_t* bsrc = Bh_g + (size_t)(n0 + row) * kw + kt * 16 + c * 4;
                cpa16(bufb + (uint32_t)dstw * 4,                    asrc, asz);
                cpa16(bufb + (uint32_t)(TILE_WORDS + dstw) * 4,     alsr, asz);
                cpa16(bufb + (uint32_t)(2 * TILE_WORDS + dstw) * 4, bsrc, 16);
            }
            asm volatile("cp.async.commit_group;\n");
        };

        issue(0, 0);

        for (int kt = 0; kt < nk; kt++) {
            const bool more = (kt + 1 < nk);
            if (more) issue(kt + 1, (kt + 1) & 1);
            if (more) { asm volatile("cp.async.wait_group 1;\n"); }
            else      { asm volatile("cp.async.wait_group 0;\n"); }
            __syncthreads();

            const uint32_t* Ah = sm + (kt & 1) * BUF_WORDS;
            const uint32_t* Al = Ah + TILE_WORDS;
            const uint32_t* Bh = Ah + 2 * TILE_WORDS;
            #pragma unroll
            for (int ks = 0; ks < 2; ks++) {
                const int kb = ks * 4;
                uint32_t ah[2][4], al[2][4];
                #pragma unroll
                for (int mt = 0; mt < 2; mt++) {
                    int r0 = warp_m * 32 + mt * 16;
                    ah[mt][0] = Ah[swz(r0 + g,     kb + tg)];
                    ah[mt][1] = Ah[swz(r0 + g + 8, kb + tg)];
                    ah[mt][2] = Ah[swz(r0 + g,     kb + tg + 8)];
                    ah[mt][3] = Ah[swz(r0 + g + 8, kb + tg + 8)];
                    al[mt][0] = Al[swz(r0 + g,     kb + tg)];
                    al[mt][1] = Al[swz(r0 + g + 8, kb + tg)];
                    al[mt][2] = Al[swz(r0 + g,     kb + tg + 8)];
                    al[mt][3] = Al[swz(r0 + g + 8, kb + tg + 8)];
                }
                #pragma unroll
                for (int nt = 0; nt < 8; nt++) {
                    int col = warp_n * 64 + nt * 8 + g;
                    uint32_t bh[2];
                    bh[0] = Bh[swz(col, kb + tg)];
                    bh[1] = Bh[swz(col, kb + tg + 8)];
                    #pragma unroll
                    for (int mt = 0; mt < 2; mt++) {
                        float* c = acc[mt][nt];
                        mma16816(c, ah[mt], bh);
                        mma16816(c, al[mt], bh);
                    }
                }
            }
            __syncthreads();
        }

        // ---- epilogue ----
        float* rowbuf = (float*)sm;
        #pragma unroll
        for (int mt = 0; mt < 2; mt++) {
            int rloc = warp_m * 32 + mt * 16 + (lane >> 2);
            int row = m0 + rloc;
            #pragma unroll
            for (int nt = 0; nt < 8; nt++) {
                int col = n0 + warp_n * 64 + nt * 8 + (lane & 3) * 2;
                float2 bb = *(const float2*)(bias + col);
                #pragma unroll
                for (int half = 0; half < 2; half++) {
                    int r = row + half * 8;
                    if (r >= M) continue;
                    float v0 = acc[mt][nt][2 * half]     + bb.x;
                    float v1 = acc[mt][nt][2 * half + 1] + bb.y;
                    if (MODE == 2) {
                        v0 = fast_gelu(v0);
                        v1 = fast_gelu(v1);
                        uint32_t h, l;
                        split_pack(v0, v1, h, l);
                        size_t w = (size_t)r * (N >> 1) + (col >> 1);
                        Chi[w] = h; Clo[w] = l;
                    } else if (MODE == 3) {
                        float2 old = *(float2*)(C + (size_t)r * N + col);
                        rowbuf[(rloc + half * 8) * 128 + (col - n0)]     = v0 + old.x;
                        rowbuf[(rloc + half * 8) * 128 + (col - n0) + 1] = v1 + old.y;
                    } else {
                        float2* dst = (float2*)(C + (size_t)r * N + col);
                        if (MODE == 1) {
                            float2 old = *dst;
                            v0 += old.x; v1 += old.y;
                        }
                        *dst = make_float2(v0, v1);
                    }
                }
            }
        }

        if (MODE == 3) {
            __syncthreads();
            float4 gg = ((const float4*)lng)[lane];
            float4 bb2 = ((const float4*)lnb)[lane];
            for (int rr = wid * 16; rr < wid * 16 + 16; rr++) {
                int r = m0 + rr;
                if (r >= M) break;
                float4 v = ((const float4*)(rowbuf + rr * 128))[lane];
                float s  = v.x + v.y + v.z + v.w;
                float sq = v.x*v.x + v.y*v.y + v.z*v.z + v.w*v.w;
                #pragma unroll
                for (int o = 16; o; o >>= 1) {
                    s  += __shfl_xor_sync(0xffffffffu, s,  o);
                    sq += __shfl_xor_sync(0xffffffffu, sq, o);
                }
                float m   = s * (1.0f / 128.0f);
                float var = sq * (1.0f / 128.0f) - m * m;
                float inv = rsqrtf(var + 1e-5f);
                ((float4*)(C + (size_t)r * 128))[lane] = v;
                float o0 = (v.x - m) * inv * gg.x + bb2.x;
                float o1 = (v.y - m) * inv * gg.y + bb2.y;
                float o2 = (v.z - m) * inv * gg.z + bb2.z;
                float o3 = (v.w - m) * inv * gg.w + bb2.w;
                uint32_t h0, l0, h1, l1;
                split_pack(o0, o1, h0, l0);
                split_pack(o2, o3, h1, l1);
                size_t base = (size_t)r * 64 + lane * 2;
                Chi[base] = h0; Chi[base + 1] = h1;
                Clo[base] = l0; Clo[base + 1] = l1;
            }
        }
        __syncthreads();   // smem (rowbuf / buffers) safe for next tile
    }
}

// ------------------- fused GATv2 node kernel (warp per dst) ------------------
__global__ void gat_node_kernel(const float* __restrict__ xlr,
                                const float* __restrict__ att,
                                const float* __restrict__ gat_b,
                                uint32_t* __restrict__ gohi, uint32_t* __restrict__ golo,
                                int N) {
    int node = (blockIdx.x * blockDim.x + threadIdx.x) >> 5;
    int lane = threadIdx.x & 31;
    if (node >= N) return;

    const float4* base = (const float4*)xlr;
    float4 r0 = base[(size_t)node * 128 + 64 + lane];
    float4 r1 = base[(size_t)node * 128 + 96 + lane];
    float4 a0 = ((const float4*)att)[lane];
    float4 a1 = ((const float4*)att)[32 + lane];

    float mA0 = -1e30f, mA1 = -1e30f, dA0 = 0.f, dA1 = 0.f;
    float mB0 = -1e30f, mB1 = -1e30f, dB0 = 0.f, dB1 = 0.f;
    float4 aA0 = make_float4(0.f,0.f,0.f,0.f), aA1 = make_float4(0.f,0.f,0.f,0.f);
    float4 aB0 = make_float4(0.f,0.f,0.f,0.f), aB1 = make_float4(0.f,0.f,0.f,0.f);

    int beg = g_off[node], end = g_off[node + 1];

    auto process = [&](int s, float& m0, float& m1, float& d0, float& d1,
                       float4& acc0, float4& acc1) {
        float4 l0 = base[(size_t)s * 128 + lane];
        float4 l1 = base[(size_t)s * 128 + 32 + lane];
        float4 e0, e1;
        e0.x = l0.x + r0.x; e0.x = e0.x > 0.f ? e0.x : 0.2f * e0.x;
        e0.y = l0.y + r0.y; e0.y = e0.y > 0.f ? e0.y : 0.2f * e0.y;
        e0.z = l0.z + r0.z; e0.z = e0.z > 0.f ? e0.z : 0.2f * e0.z;
        e0.w = l0.w + r0.w; e0.w = e0.w > 0.f ? e0.w : 0.2f * e0.w;
        e1.x = l1.x + r1.x; e1.x = e1.x > 0.f ? e1.x : 0.2f * e1.x;
        e1.y = l1.y + r1.y; e1.y = e1.y > 0.f ? e1.y : 0.2f * e1.y;
        e1.z = l1.z + r1.z; e1.z = e1.z > 0.f ? e1.z : 0.2f * e1.z;
        e1.w = l1.w + r1.w; e1.w = e1.w > 0.f ? e1.w : 0.2f * e1.w;
        float p0 = e0.x * a0.x + e0.y * a0.y + e0.z * a0.z + e0.w * a0.w;
        float p1 = e1.x * a1.x + e1.y * a1.y + e1.z * a1.z + e1.w * a1.w;
        #pragma unroll
        for (int o = 16; o; o >>= 1) {
            p0 += __shfl_xor_sync(0xffffffffu, p0, o);
            p1 += __shfl_xor_sync(0xffffffffu, p1, o);
        }
        float nm0 = fmaxf(m0, p0);
        float f0 = __expf(m0 - nm0);
        float w0 = __expf(p0 - nm0);
        m0 = nm0;
        d0 = d0 * f0 + w0;
        acc0.x = acc0.x * f0 + w0 * l0.x;
        acc0.y = acc0.y * f0 + w0 * l0.y;
        acc0.z = acc0.z * f0 + w0 * l0.z;
        acc0.w = acc0.w * f0 + w0 * l0.w;
        float nm1 = fmaxf(m1, p1);
        float f1 = __expf(m1 - nm1);
        float w1 = __expf(p1 - nm1);
        m1 = nm1;
        d1 = d1 * f1 + w1;
        acc1.x = acc1.x * f1 + w1 * l1.x;
        acc1.y = acc1.y * f1 + w1 * l1.y;
        acc1.z = acc1.z * f1 + w1 * l1.z;
        acc1.w = acc1.w * f1 + w1 * l1.w;
    };

    int i = beg;
    for (; i + 1 < end; i += 2) {
        int sA = g_esrc[i];
        int sB = g_esrc[i + 1];
        process(sA, mA0, mA1, dA0, dA1, aA0, aA1);
        process(sB, mB0, mB1, dB0, dB1, aB0, aB1);
    }
    if (i < end) process(g_esrc[i], mA0, mA1, dA0, dA1, aA0, aA1);

    {
        float m = fmaxf(mA0, mB0);
        float fA = __expf(mA0 - m), fB = __expf(mB0 - m);
        dA0 = dA0 * fA + dB0 * fB;
        aA0.x = aA0.x * fA + aB0.x * fB;
        aA0.y = aA0.y * fA + aB0.y * fB;
        aA0.z = aA0.z * fA + aB0.z * fB;
        aA0.w = aA0.w * fA + aB0.w * fB;
        m = fmaxf(mA1, mB1);
        fA = __expf(mA1 - m); fB = __expf(mB1 - m);
        dA1 = dA1 * fA + dB1 * fB;
        aA1.x = aA1.x * fA + aB1.x * fB;
        aA1.y = aA1.y * fA + aB1.y * fB;
        aA1.z = aA1.z * fA + aB1.z * fB;
        aA1.w = aA1.w * fA + aB1.w * fB;
    }

    float inv0 = 1.0f / (dA0 + 1e-16f);
    float inv1 = 1.0f / (dA1 + 1e-16f);
    const float4* gb4 = (const float4*)gat_b;
    float4 b0 = gb4[lane];
    float4 b1 = gb4[32 + lane];
    float o0 = aA0.x * inv0 + b0.x, o1 = aA0.y * inv0 + b0.y;
    float o2 = aA0.z * inv0 + b0.z, o3 = aA0.w * inv0 + b0.w;
    float o4 = aA1.x * inv1 + b1.x, o5 = aA1.y * inv1 + b1.y;
    float o6 = aA1.z * inv1 + b1.z, o7 = aA1.w * inv1 + b1.w;

    uint32_t h0, l0w, h1, l1w, h2, l2w, h3, l3w;
    split_pack(o0, o1, h0, l0w);
    split_pack(o2, o3, h1, l1w);
    split_pack(o4, o5, h2, l2w);
    split_pack(o6, o7, h3, l3w);
    size_t rb = (size_t)node * 128;
    gohi[rb + lane * 2]          = h0;  golo[rb + lane * 2]          = l0w;
    gohi[rb + lane * 2 + 1]      = h1;  golo[rb + lane * 2 + 1]      = l1w;
    gohi[rb + 64 + lane * 2]     = h2;  golo[rb + 64 + lane * 2]     = l2w;
    gohi[rb + 64 + lane * 2 + 1] = h3;  golo[rb + 64 + lane * 2 + 1] = l3w;
}

// ------------------------- launch --------------------------------------------
static inline int pgrid(int ntiles) { return ntiles < PERSIST_BLOCKS ? ntiles : PERSIST_BLOCKS; }

extern "C" void kernel_launch(void* const* d_in, const int* in_sizes, int n_in,
                              void* d_out, int out_size) {
    const float* x_in   = (const float*)d_in[0];
    const void*  edges  = d_in[1];
    const float* ln1_g  = (const float*)d_in[2];
    const float* ln1_b  = (const float*)d_in[3];
    const float* Wl     = (const float*)d_in[4];
    const float* bl     = (const float*)d_in[5];
    const float* Wr     = (const float*)d_in[6];
    const float* br     = (const float*)d_in[7];
    const float* att    = (const float*)d_in[8];
    const float* gat_b  = (const float*)d_in[9];
    const float* projW  = (const float*)d_in[10];
    const float* projb  = (const float*)d_in[11];
    const float* ln2_g  = (const float*)d_in[12];
    const float* ln2_b  = (const float*)d_in[13];
    const float* W1     = (const float*)d_in[14];
    const float* b1     = (const float*)d_in[15];
    const float* W2     = (const float*)d_in[16];
    const float* b2     = (const float*)d_in[17];

    const int N = in_sizes[0] / DIM;
    const int E = in_sizes[1] / 2;
    float* x = (float*)d_out;

    cudaFuncSetAttribute(gemm_kernel<0>, cudaFuncAttributeMaxDynamicSharedMemorySize, GEMM_SMEM);
    cudaFuncSetAttribute(gemm_kernel<1>, cudaFuncAttributeMaxDynamicSharedMemorySize, GEMM_SMEM);
    cudaFuncSetAttribute(gemm_kernel<2>, cudaFuncAttributeMaxDynamicSharedMemorySize, GEMM_SMEM);
    cudaFuncSetAttribute(gemm_kernel<3>, cudaFuncAttributeMaxDynamicSharedMemorySize, GEMM_SMEM3);

    void *p_xlr, *p_hhi, *p_hlo, *p_gohi, *p_golo, *p_mhi, *p_mlo, *p_wb, *p_blr;
    cudaGetSymbolAddress(&p_xlr, g_xlr);
    cudaGetSymbolAddress(&p_hhi, g_h_hi);
    cudaGetSymbolAddress(&p_hlo, g_h_lo);
    cudaGetSymbolAddress(&p_gohi, g_go_hi);
    cudaGetSymbolAddress(&p_golo, g_go_lo);
    cudaGetSymbolAddress(&p_mhi, g_mid_hi);
    cudaGetSymbolAddress(&p_mlo, g_mid_lo);
    cudaGetSymbolAddress(&p_wb, g_wb);
    cudaGetSymbolAddress(&p_blr, g_blr);
    float* xlr = (float*)p_xlr;
    uint32_t* hhi = (uint32_t*)p_hhi;
    uint32_t* hlo = (uint32_t*)p_hlo;
    uint32_t* gohi = (uint32_t*)p_gohi;
    uint32_t* golo = (uint32_t*)p_golo;
    uint32_t* mhi = (uint32_t*)p_mhi;
    uint32_t* mlo = (uint32_t*)p_mlo;
    uint32_t* wb = (uint32_t*)p_wb;
    float* blr = (float*)p_blr;

    cudaMemcpyAsync(x, x_in, (size_t)N * DIM * sizeof(float), cudaMemcpyDeviceToDevice);

    const int nb = (N + 1023) / 1024;
    detect_kernel<<<1, 256>>>(edges, E, N);
    clear_deg_kernel<<<(N + 255) / 256, 256>>>(N);
    decode_hist_kernel<<<(E + 255) / 256, 256>>>(edges, E);
    scanA_kernel<<<nb, 1024>>>(N);
    scanB_kernel<<<1, 32>>>(nb);
    scanC_kernel<<<(N + 255) / 256, 256>>>(N);
    scatter_kernel<<<(E + 255) / 256, 256>>>(E);

    wconv_all_kernel<<<(2 * LWORDS + 255) / 256, 256>>>(Wl, Wr, projW, W1, W2);
    bconcat_kernel<<<4, 256>>>(bl, br);

    const int ln_blocks = (N + 7) / 8;
    const int mtiles = (N + 127) / 128;

    ln_kernel<<<ln_blocks, 256>>>(x, ln1_g, ln1_b, hhi, hlo, N);

    for (int l = 0; l < 2; l++) {
        size_t off = (size_t)l * LWORDS;
        const uint32_t* wlr = wb + off;
        const uint32_t* pj  = wb + off + 32768;
        const uint32_t* w1  = wb + off + 49152;
        const uint32_t* w2  = wb + off + 81920;
        const float* at_l = att + (size_t)l * HD;
        const float* gb_l = gat_b + (size_t)l * HD;
        const float* pb_l = projb + (size_t)l * DIM;
        const float* b1_l = b1 + (size_t)l * MLPD;
        const float* b2_l = b2 + (size_t)l * DIM;

        gemm_kernel<0><<<pgrid(4 * mtiles), 256, GEMM_SMEM>>>(
            hhi, hlo, wlr, blr + (size_t)l * 512, xlr, nullptr, nullptr,
            nullptr, nullptr, N, DIM, 512);
        gat_node_kernel<<<(N + 7) / 8, 256>>>(xlr, at_l, gb_l, gohi, golo, N);
        gemm_kernel<3><<<pgrid(mtiles), 256, GEMM_SMEM3>>>(
            gohi, golo, pj, pb_l, x, hhi, hlo,
            ln2_g + (size_t)l * DIM, ln2_b + (size_t)l * DIM, N, HD, DIM);
        gemm_kernel<2><<<pgrid(4 * mtiles), 256, GEMM_SMEM>>>(
            hhi, hlo, w1, b1_l, nullptr, mhi, mlo,
            nullptr, nullptr, N, DIM, MLPD);
        if (l == 0) {
            gemm_kernel<3><<<pgrid(mtiles), 256, GEMM_SMEM3>>>(
                mhi, mlo, w2, b2_l, x, hhi, hlo,
                ln1_g + DIM, ln1_b + DIM, N, MLPD, DIM);
        } else {
            gemm_kernel<1><<<pgrid(mtiles), 256, GEMM_SMEM>>>(
                mhi, mlo, w2, b2_l, x, nullptr, nullptr,
                nullptr, nullptr, N, MLPD, DIM);
        }
    }
}

// round 14
// speedup vs baseline: 1.0642x; 1.0163x over previous
#include <cuda_runtime.h>
#include <cuda_fp16.h>
#include <math.h>
#include <stdint.h>

// ----------------------------------------------------------------------------
// GATv2 Transformer. GEMMs: fp16 mma.sync, A split hi+lo, weights fp16,
// cp.async double buffer, persistent-CTA tiling with CROSS-TILE prefetch
// (MODE 3 prefetches after its LN epilogue). Edge: CSR + online softmax.
// ----------------------------------------------------------------------------

#define MAXN 50000
#define MAXE 800000
#define DIM 128
#define HD 256
#define MLPD 512
#define LWORDS 114688
#define PERSIST_BLOCKS 296     // 148 SMs x 2 CTAs

// ------------------------- scratch (device globals) -------------------------
__device__ __align__(256) float    g_xlr [(size_t)MAXN * 512];
__device__ __align__(256) uint32_t g_h_hi [(size_t)MAXN * (DIM/2)];
__device__ __align__(256) uint32_t g_h_lo [(size_t)MAXN * (DIM/2)];
__device__ __align__(256) uint32_t g_go_hi[(size_t)MAXN * (HD/2)];
__device__ __align__(256) uint32_t g_go_lo[(size_t)MAXN * (HD/2)];
__device__ __align__(256) uint32_t g_mid_hi[(size_t)MAXN * (MLPD/2)];
__device__ __align__(256) uint32_t g_mid_lo[(size_t)MAXN * (MLPD/2)];
__device__ __align__(256) uint32_t g_wb[2 * LWORDS];
__device__ __align__(256) float    g_blr[2 * 512];
// CSR
__device__ __align__(256) int g_src[MAXE];
__device__ __align__(256) int g_dst[MAXE];
__device__ __align__(256) int g_esrc[MAXE];
__device__ __align__(256) int g_deg[MAXN];
__device__ __align__(256) int g_off[MAXN + 1];
__device__ __align__(256) int g_pos[MAXN];
__device__ __align__(256) int g_bsum[64];
__device__ __align__(256) int g_boff[64];
__device__ int g_is64;

// ------------------------- helpers -------------------------
__device__ __forceinline__ void split_pack(float x, float y, uint32_t& hi, uint32_t& lo) {
    __half hx = __float2half_rn(x);
    __half hy = __float2half_rn(y);
    __half lx = __float2half_rn(x - __half2float(hx));
    __half ly = __float2half_rn(y - __half2float(hy));
    hi = ((uint32_t)__half_as_ushort(hy) << 16) | (uint32_t)__half_as_ushort(hx);
    lo = ((uint32_t)__half_as_ushort(ly) << 16) | (uint32_t)__half_as_ushort(lx);
}
__device__ __forceinline__ uint32_t pack_h(float x, float y) {
    return ((uint32_t)__half_as_ushort(__float2half_rn(y)) << 16)
         | (uint32_t)__half_as_ushort(__float2half_rn(x));
}
__device__ __forceinline__ float fast_gelu(float u) {
    float z2 = 1.5957691216057308f * (u + 0.044715f * u * u * u);
    return u * __fdividef(1.0f, 1.0f + __expf(-z2));
}

// ------------------------- edge dtype detect / decode+hist -------------------
__global__ void detect_kernel(const void* edges, int E, int N) {
    __shared__ int bad;
    if (threadIdx.x == 0) bad = 0;
    __syncthreads();
    const long long* p = (const long long*)edges;
    int n = E < 2048 ? E : 2048;
    for (int i = threadIdx.x; i < n; i += blockDim.x) {
        long long v = p[i];
        if (v < 0 || v >= (long long)N) atomicOr(&bad, 1);
    }
    __syncthreads();
    if (threadIdx.x == 0) g_is64 = bad ? 0 : 1;
}

__global__ void clear_deg_kernel(int N) {
    int i = blockIdx.x * blockDim.x + threadIdx.x;
    if (i < N) g_deg[i] = 0;
}

__global__ void decode_hist_kernel(const void* edges, int E) {
    int i = blockIdx.x * blockDim.x + threadIdx.x;
    if (i >= E) return;
    int s, d;
    if (g_is64) {
        const long long* p = (const long long*)edges;
        s = (int)p[i];
        d = (int)p[(size_t)E + i];
    } else {
        const int* p = (const int*)edges;
        s = p[i];
        d = p[(size_t)E + i];
    }
    g_src[i] = s;
    g_dst[i] = d;
    atomicAdd(&g_deg[d], 1);
}

// ---- 3-phase parallel scan ----
__global__ void scanA_kernel(int N) {
    int t = threadIdx.x;
    int i = blockIdx.x * 1024 + t;
    int lane = t & 31, w = t >> 5;
    int v = (i < N) ? g_deg[i] : 0;
    int s = v;
    #pragma unroll
    for (int o = 1; o < 32; o <<= 1) {
        int u = __shfl_up_sync(0xffffffffu, s, o);
        if (lane >= o) s += u;
    }
    __shared__ int wt[32];
    if (lane == 31) wt[w] = s;
    __syncthreads();
    if (w == 0) {
        int x = wt[lane];
        #pragma unroll
        for (int o = 1; o < 32; o <<= 1) {
            int u = __shfl_up_sync(0xffffffffu, x, o);
            if (lane >= o) x += u;
        }
        wt[lane] = x;
    }
    __syncthreads();
    if (w) s += wt[w - 1];
    if (i < N) g_off[i + 1] = s;
    if (t == 1023) g_bsum[blockIdx.x] = s;
}

__global__ void scanB_kernel(int nb) {
    int lane = threadIdx.x;
    int v0 = (lane < nb) ? g_bsum[lane] : 0;
    int v1 = (32 + lane < nb) ? g_bsum[32 + lane] : 0;
    int s0 = v0;
    #pragma unroll
    for (int o = 1; o < 32; o <<= 1) {
        int u = __shfl_up_sync(0xffffffffu, s0, o);
        if (lane >= o) s0 += u;
    }
    int tot0 = __shfl_sync(0xffffffffu, s0, 31);
    int s1 = v1;
    #pragma unroll
    for (int o = 1; o < 32; o <<= 1) {
        int u = __shfl_up_sync(0xffffffffu, s1, o);
        if (lane >= o) s1 += u;
    }
    if (lane < nb) g_boff[lane] = s0 - v0;
    if (32 + lane < nb) g_boff[32 + lane] = tot0 + s1 - v1;
}

__global__ void scanC_kernel(int N) {
    int i = blockIdx.x * blockDim.x + threadIdx.x;
    if (i == 0) g_off[0] = 0;
    if (i >= N) return;
    int b = i >> 10;
    int inc = g_off[i + 1] + g_boff[b];
    g_off[i + 1] = inc;
    g_pos[i] = inc - g_deg[i];
}

__global__ void scatter_kernel(int E) {
    int i = blockIdx.x * blockDim.x + threadIdx.x;
    if (i >= E) return;
    int p = atomicAdd(&g_pos[g_dst[i]], 1);
    g_esrc[p] = g_src[i];
}

// ---------------- fused weight convert (single fp16) -------------------------
__global__ void wconv_all_kernel(const float* __restrict__ Wl, const float* __restrict__ Wr,
                                 const float* __restrict__ pj, const float* __restrict__ W1,
                                 const float* __restrict__ W2) {
    int idx = blockIdx.x * blockDim.x + threadIdx.x;
    if (idx >= 2 * LWORDS) return;
    int layer = idx / LWORDS;
    int r = idx - layer * LWORDS;
    const float* W; int K, N;
    if (r < 16384)      { W = Wl + (size_t)layer * 32768; K = 128; N = 256; }
    else if (r < 32768) { W = Wr + (size_t)layer * 32768; r -= 16384; K = 128; N = 256; }
    else if (r < 49152) { W = pj + (size_t)layer * 32768; r -= 32768; K = 256; N = 128; }
    else if (r < 81920) { W = W1 + (size_t)layer * 65536; r -= 49152; K = 128; N = 512; }
    else                { W = W2 + (size_t)layer * 65536; r -= 81920; K = 512; N = 128; }
    int kw = K >> 1;
    int n = r / kw, kp = r - n * kw;
    float x = W[(size_t)(2 * kp) * N + n];
    float y = W[(size_t)(2 * kp + 1) * N + n];
    g_wb[idx] = pack_h(x, y);
}

__global__ void bconcat_kernel(const float* __restrict__ bl, const float* __restrict__ br) {
    int i = threadIdx.x + blockIdx.x * blockDim.x;
    if (i >= 1024) return;
    int layer = i >> 9, j = i & 511;
    float v = (j < 256) ? bl[layer * HD + j] : br[layer * HD + j - 256];
    g_blr[layer * 512 + j] = v;
}

// ------------------------- standalone layernorm ------------------------------
__global__ void ln_kernel(const float* __restrict__ x, const float* __restrict__ g,
                          const float* __restrict__ b,
                          uint32_t* __restrict__ ohi, uint32_t* __restrict__ olo, int N) {
    int row = (blockIdx.x * blockDim.x + threadIdx.x) >> 5;
    int lane = threadIdx.x & 31;
    if (row >= N) return;
    const float4* xr = (const float4*)x + (size_t)row * 32;
    float4 v = xr[lane];
    float s  = v.x + v.y + v.z + v.w;
    float sq = v.x*v.x + v.y*v.y + v.z*v.z + v.w*v.w;
    #pragma unroll
    for (int o = 16; o; o >>= 1) {
        s  += __shfl_xor_sync(0xffffffffu, s,  o);
        sq += __shfl_xor_sync(0xffffffffu, sq, o);
    }
    float m   = s * (1.0f / 128.0f);
    float var = sq * (1.0f / 128.0f) - m * m;
    float inv = rsqrtf(var + 1e-5f);
    float4 gg = ((const float4*)g)[lane];
    float4 bb = ((const float4*)b)[lane];
    float o0 = (v.x - m) * inv * gg.x + bb.x;
    float o1 = (v.y - m) * inv * gg.y + bb.y;
    float o2 = (v.z - m) * inv * gg.z + bb.z;
    float o3 = (v.w - m) * inv * gg.w + bb.w;
    uint32_t h0, l0, h1, l1;
    split_pack(o0, o1, h0, l0);
    split_pack(o2, o3, h1, l1);
    size_t base = (size_t)row * 64 + lane * 2;
    ohi[base] = h0; ohi[base + 1] = h1;
    olo[base] = l0; olo[base + 1] = l1;
}

// ------------------------- tensor-core GEMM --------------------------------
__device__ __forceinline__ void mma16816(float* c, const uint32_t* a, const uint32_t* b) {
    asm volatile(
        "mma.sync.aligned.m16n8k16.row.col.f32.f16.f16.f32 "
        "{%0,%1,%2,%3}, {%4,%5,%6,%7}, {%8,%9}, {%0,%1,%2,%3};"
        : "+f"(c[0]), "+f"(c[1]), "+f"(c[2]), "+f"(c[3])
        : "r"(a[0]), "r"(a[1]), "r"(a[2]), "r"(a[3]), "r"(b[0]), "r"(b[1]));
}

__device__ __forceinline__ void cpa16(uint32_t dst, const void* src, int bytes) {
    asm volatile("cp.async.cg.shared.global [%0], [%1], 16, %2;\n"
                 :: "r"(dst), "l"(src), "r"(bytes));
}

__device__ __forceinline__ int swz(int row, int kp) {
    return (row << 4) | (((kp >> 2) ^ ((row >> 1) & 3)) << 2) | (kp & 3);
}

#define TILE_WORDS 2048
#define BUF_WORDS  (3 * TILE_WORDS)
#define GEMM_SMEM  (2 * BUF_WORDS * 4)       // 48 KB
#define GEMM_SMEM3 65536                     // MODE 3 rowbuf

// MODE 0: store fp32; 1: accumulate fp32; 2: GELU then split hi/lo;
// MODE 3: accumulate + fused LayerNorm -> writes x (C) and split h (N==128)
// Persistent blocks; next tile's k0 prefetched across the epilogue
// (inline for MODE!=3; after the LN epilogue + sync for MODE 3).
template<int MODE>
__global__ __launch_bounds__(256, 2)
void gemm_kernel(const uint32_t* __restrict__ Ahi, const uint32_t* __restrict__ Alo,
                 const uint32_t* __restrict__ Bh_g,
                 const float* __restrict__ bias, float* __restrict__ C,
                 uint32_t* __restrict__ Chi, uint32_t* __restrict__ Clo,
                 const float* __restrict__ lng, const float* __restrict__ lnb,
                 int M, int K, int N) {
    extern __shared__ uint32_t sm[];

    const int tid  = threadIdx.x;
    const int lane = tid & 31;
    const int wid  = tid >> 5;
    const int warp_m = wid & 3;
    const int warp_n = wid >> 2;
    const int g  = lane >> 2;
    const int tg = lane & 3;
    const int kw = K >> 1;
    const int nk = K >> 5;                 // even for all K used (4, 8, 16)
    const int nx = N >> 7;
    const int ntiles = nx * ((M + 127) >> 7);

    const uint32_t sbase = (uint32_t)__cvta_generic_to_shared(sm);

    // issue k-tile kt of output tile t into smem buffer b
    auto issue = [&](int t, int kt, int b) {
        const int n0_ = (t % nx) * 128;
        const int m0_ = (t / nx) * 128;
        uint32_t bufb = sbase + (uint32_t)(b * BUF_WORDS) * 4;
        #pragma unroll
        for (int q = 0; q < 2; q++) {
            int chunk = tid + q * 256;
            int row = chunk >> 2, c = chunk & 3;
            int dstw = (row << 4) | ((c ^ ((row >> 1) & 3)) << 2);
            int asz = (m0_ + row < M) ? 16 : 0;
            const uint32_t* asrc = Ahi + (size_t)(m0_ + row) * kw + kt * 16 + c * 4;
            const uint32_t* alsr = Alo + (size_t)(m0_ + row) * kw + kt * 16 + c * 4;
            const uint32_t* bsrc = Bh_g + (size_t)(n0_ + row) * kw + kt * 16 + c * 4;
            cpa16(bufb + (uint32_t)dstw * 4,                    asrc, asz);
            cpa16(bufb + (uint32_t)(TILE_WORDS + dstw) * 4,     alsr, asz);
            cpa16(bufb + (uint32_t)(2 * TILE_WORDS + dstw) * 4, bsrc, 16);
        }
        asm volatile("cp.async.commit_group;\n");
    };

    if (blockIdx.x < ntiles) issue(blockIdx.x, 0, 0);

    for (int tile = blockIdx.x; tile < ntiles; tile += gridDim.x) {
        const int n0 = (tile % nx) * 128;
        const int m0 = (tile / nx) * 128;

        float acc[2][8][4];
        #pragma unroll
        for (int i = 0; i < 2; i++)
            #pragma unroll
            for (int j = 0; j < 8; j++)
                #pragma unroll
                for (int r = 0; r < 4; r++) acc[i][j][r] = 0.0f;

        for (int kt = 0; kt < nk; kt++) {
            bool issued;
            if (kt + 1 < nk) {
                issue(tile, kt + 1, (kt + 1) & 1);
                issued = true;
            } else if (MODE != 3 && tile + gridDim.x < ntiles) {
                issue(tile + gridDim.x, 0, 0);   // cross-tile prefetch (nk even -> buf 0)
                issued = true;
            } else {
                issued = false;
            }
            if (issued) { asm volatile("cp.async.wait_group 1;\n"); }
            else        { asm volatile("cp.async.wait_group 0;\n"); }
            __syncthreads();

            const uint32_t* Ah = sm + (kt & 1) * BUF_WORDS;
            const uint32_t* Al = Ah + TILE_WORDS;
            const uint32_t* Bh = Ah + 2 * TILE_WORDS;
            #pragma unroll
            for (int ks = 0; ks < 2; ks++) {
                const int kb = ks * 4;
                uint32_t ah[2][4], al[2][4];
                #pragma unroll
                for (int mt = 0; mt < 2; mt++) {
                    int r0 = warp_m * 32 + mt * 16;
                    ah[mt][0] = Ah[swz(r0 + g,     kb + tg)];
                    ah[mt][1] = Ah[swz(r0 + g + 8, kb + tg)];
                    ah[mt][2] = Ah[swz(r0 + g,     kb + tg + 8)];
                    ah[mt][3] = Ah[swz(r0 + g + 8, kb + tg + 8)];
                    al[mt][0] = Al[swz(r0 + g,     kb + tg)];
                    al[mt][1] = Al[swz(r0 + g + 8, kb + tg)];
                    al[mt][2] = Al[swz(r0 + g,     kb + tg + 8)];
                    al[mt][3] = Al[swz(r0 + g + 8, kb + tg + 8)];
                }
                #pragma unroll
                for (int nt = 0; nt < 8; nt++) {
                    int col = warp_n * 64 + nt * 8 + g;
                    uint32_t bh[2];
                    bh[0] = Bh[swz(col, kb + tg)];
                    bh[1] = Bh[swz(col, kb + tg + 8)];
                    #pragma unroll
                    for (int mt = 0; mt < 2; mt++) {
                        float* c = acc[mt][nt];
                        mma16816(c, ah[mt], bh);
                        mma16816(c, al[mt], bh);
                    }
                }
            }
            __syncthreads();
        }

        // ---- epilogue (no smem except MODE 3) ----
        float* rowbuf = (float*)sm;
        #pragma unroll
        for (int mt = 0; mt < 2; mt++) {
            int rloc = warp_m * 32 + mt * 16 + (lane >> 2);
            int row = m0 + rloc;
            #pragma unroll
            for (int nt = 0; nt < 8; nt++) {
                int col = n0 + warp_n * 64 + nt * 8 + (lane & 3) * 2;
                float2 bb = *(const float2*)(bias + col);
                #pragma unroll
                for (int half = 0; half < 2; half++) {
                    int r = row + half * 8;
                    if (r >= M) continue;
                    float v0 = acc[mt][nt][2 * half]     + bb.x;
                    float v1 = acc[mt][nt][2 * half + 1] + bb.y;
                    if (MODE == 2) {
                        v0 = fast_gelu(v0);
                        v1 = fast_gelu(v1);
                        uint32_t h, l;
                        split_pack(v0, v1, h, l);
                        size_t w = (size_t)r * (N >> 1) + (col >> 1);
                        Chi[w] = h; Clo[w] = l;
                    } else if (MODE == 3) {
                        float2 old = *(float2*)(C + (size_t)r * N + col);
                        rowbuf[(rloc + half * 8) * 128 + (col - n0)]     = v0 + old.x;
                        rowbuf[(rloc + half * 8) * 128 + (col - n0) + 1] = v1 + old.y;
                    } else {
                        float2* dst = (float2*)(C + (size_t)r * N + col);
                        if (MODE == 1) {
                            float2 old = *dst;
                            v0 += old.x; v1 += old.y;
                        }
                        *dst = make_float2(v0, v1);
                    }
                }
            }
        }

        if (MODE == 3) {
            __syncthreads();
            float4 gg = ((const float4*)lng)[lane];
            float4 bb2 = ((const float4*)lnb)[lane];
            for (int rr = wid * 16; rr < wid * 16 + 16; rr++) {
                int r = m0 + rr;
                if (r >= M) break;
                float4 v = ((const float4*)(rowbuf + rr * 128))[lane];
                float s  = v.x + v.y + v.z + v.w;
                float sq = v.x*v.x + v.y*v.y + v.z*v.z + v.w*v.w;
                #pragma unroll
                for (int o = 16; o; o >>= 1) {
                    s  += __shfl_xor_sync(0xffffffffu, s,  o);
                    sq += __shfl_xor_sync(0xffffffffu, sq, o);
                }
                float m   = s * (1.0f / 128.0f);
                float var = sq * (1.0f / 128.0f) - m * m;
                float inv = rsqrtf(var + 1e-5f);
                ((float4*)(C + (size_t)r * 128))[lane] = v;
                float o0 = (v.x - m) * inv * gg.x + bb2.x;
                float o1 = (v.y - m) * inv * gg.y + bb2.y;
                float o2 = (v.z - m) * inv * gg.z + bb2.z;
                float o3 = (v.w - m) * inv * gg.w + bb2.w;
                uint32_t h0, l0, h1, l1;
                split_pack(o0, o1, h0, l0);
                split_pack(o2, o3, h1, l1);
                size_t base = (size_t)r * 64 + lane * 2;
                Chi[base] = h0; Chi[base + 1] = h1;
                Clo[base] = l0; Clo[base + 1] = l1;
            }
            __syncthreads();   // rowbuf reads done -> buffers reusable
            if (tile + gridDim.x < ntiles)
                issue(tile + gridDim.x, 0, 0);   // MODE 3 seeds its next tile here
        }
    }
}

// ------------------- fused GATv2 node kernel (warp per dst) ------------------
__global__ void gat_node_kernel(const float* __restrict__ xlr,
                                const float* __restrict__ att,
                                const float* __restrict__ gat_b,
                                uint32_t* __restrict__ gohi, uint32_t* __restrict__ golo,
                                int N) {
    int node = (blockIdx.x * blockDim.x + threadIdx.x) >> 5;
    int lane = threadIdx.x & 31;
    if (node >= N) return;

    const float4* base = (const float4*)xlr;
    float4 r0 = base[(size_t)node * 128 + 64 + lane];
    float4 r1 = base[(size_t)node * 128 + 96 + lane];
    float4 a0 = ((const float4*)att)[lane];
    float4 a1 = ((const float4*)att)[32 + lane];

    float mA0 = -1e30f, mA1 = -1e30f, dA0 = 0.f, dA1 = 0.f;
    float mB0 = -1e30f, mB1 = -1e30f, dB0 = 0.f, dB1 = 0.f;
    float4 aA0 = make_float4(0.f,0.f,0.f,0.f), aA1 = make_float4(0.f,0.f,0.f,0.f);
    float4 aB0 = make_float4(0.f,0.f,0.f,0.f), aB1 = make_float4(0.f,0.f,0.f,0.f);

    int beg = g_off[node], end = g_off[node + 1];

    auto process = [&](int s, float& m0, float& m1, float& d0, float& d1,
                       float4& acc0, float4& acc1) {
        float4 l0 = base[(size_t)s * 128 + lane];
        float4 l1 = base[(size_t)s * 128 + 32 + lane];
        float4 e0, e1;
        e0.x = l0.x + r0.x; e0.x = e0.x > 0.f ? e0.x : 0.2f * e0.x;
        e0.y = l0.y + r0.y; e0.y = e0.y > 0.f ? e0.y : 0.2f * e0.y;
        e0.z = l0.z + r0.z; e0.z = e0.z > 0.f ? e0.z : 0.2f * e0.z;
        e0.w = l0.w + r0.w; e0.w = e0.w > 0.f ? e0.w : 0.2f * e0.w;
        e1.x = l1.x + r1.x; e1.x = e1.x > 0.f ? e1.x : 0.2f * e1.x;
        e1.y = l1.y + r1.y; e1.y = e1.y > 0.f ? e1.y : 0.2f * e1.y;
        e1.z = l1.z + r1.z; e1.z = e1.z > 0.f ? e1.z : 0.2f * e1.z;
        e1.w = l1.w + r1.w; e1.w = e1.w > 0.f ? e1.w : 0.2f * e1.w;
        float p0 = e0.x * a0.x + e0.y * a0.y + e0.z * a0.z + e0.w * a0.w;
        float p1 = e1.x * a1.x + e1.y * a1.y + e1.z * a1.z + e1.w * a1.w;
        #pragma unroll
        for (int o = 16; o; o >>= 1) {
            p0 += __shfl_xor_sync(0xffffffffu, p0, o);
            p1 += __shfl_xor_sync(0xffffffffu, p1, o);
        }
        float nm0 = fmaxf(m0, p0);
        float f0 = __expf(m0 - nm0);
        float w0 = __expf(p0 - nm0);
        m0 = nm0;
        d0 = d0 * f0 + w0;
        acc0.x = acc0.x * f0 + w0 * l0.x;
        acc0.y = acc0.y * f0 + w0 * l0.y;
        acc0.z = acc0.z * f0 + w0 * l0.z;
        acc0.w = acc0.w * f0 + w0 * l0.w;
        float nm1 = fmaxf(m1, p1);
        float f1 = __expf(m1 - nm1);
        float w1 = __expf(p1 - nm1);
        m1 = nm1;
        d1 = d1 * f1 + w1;
        acc1.x = acc1.x * f1 + w1 * l1.x;
        acc1.y = acc1.y * f1 + w1 * l1.y;
        acc1.z = acc1.z * f1 + w1 * l1.z;
        acc1.w = acc1.w * f1 + w1 * l1.w;
    };

    int i = beg;
    for (; i + 1 < end; i += 2) {
        int sA = g_esrc[i];
        int sB = g_esrc[i + 1];
        process(sA, mA0, mA1, dA0, dA1, aA0, aA1);
        process(sB, mB0, mB1, dB0, dB1, aB0, aB1);
    }
    if (i < end) process(g_esrc[i], mA0, mA1, dA0, dA1, aA0, aA1);

    {
        float m = fmaxf(mA0, mB0);
        float fA = __expf(mA0 - m), fB = __expf(mB0 - m);
        dA0 = dA0 * fA + dB0 * fB;
        aA0.x = aA0.x * fA + aB0.x * fB;
        aA0.y = aA0.y * fA + aB0.y * fB;
        aA0.z = aA0.z * fA + aB0.z * fB;
        aA0.w = aA0.w * fA + aB0.w * fB;
        m = fmaxf(mA1, mB1);
        fA = __expf(mA1 - m); fB = __expf(mB1 - m);
        dA1 = dA1 * fA + dB1 * fB;
        aA1.x = aA1.x * fA + aB1.x * fB;
        aA1.y = aA1.y * fA + aB1.y * fB;
        aA1.z = aA1.z * fA + aB1.z * fB;
        aA1.w = aA1.w * fA + aB1.w * fB;
    }

    float inv0 = 1.0f / (dA0 + 1e-16f);
    float inv1 = 1.0f / (dA1 + 1e-16f);
    const float4* gb4 = (const float4*)gat_b;
    float4 b0 = gb4[lane];
    float4 b1 = gb4[32 + lane];
    float o0 = aA0.x * inv0 + b0.x, o1 = aA0.y * inv0 + b0.y;
    float o2 = aA0.z * inv0 + b0.z, o3 = aA0.w * inv0 + b0.w;
    float o4 = aA1.x * inv1 + b1.x, o5 = aA1.y * inv1 + b1.y;
    float o6 = aA1.z * inv1 + b1.z, o7 = aA1.w * inv1 + b1.w;

    uint32_t h0, l0w, h1, l1w, h2, l2w, h3, l3w;
    split_pack(o0, o1, h0, l0w);
    split_pack(o2, o3, h1, l1w);
    split_pack(o4, o5, h2, l2w);
    split_pack(o6, o7, h3, l3w);
    size_t rb = (size_t)node * 128;
    gohi[rb + lane * 2]          = h0;  golo[rb + lane * 2]          = l0w;
    gohi[rb + lane * 2 + 1]      = h1;  golo[rb + lane * 2 + 1]      = l1w;
    gohi[rb + 64 + lane * 2]     = h2;  golo[rb + 64 + lane * 2]     = l2w;
    gohi[rb + 64 + lane * 2 + 1] = h3;  golo[rb + 64 + lane * 2 + 1] = l3w;
}

// ------------------------- launch --------------------------------------------
static inline int pgrid(int ntiles) { return ntiles < PERSIST_BLOCKS ? ntiles : PERSIST_BLOCKS; }

extern "C" void kernel_launch(void* const* d_in, const int* in_sizes, int n_in,
                              void* d_out, int out_size) {
    const float* x_in   = (const float*)d_in[0];
    const void*  edges  = d_in[1];
    const float* ln1_g  = (const float*)d_in[2];
    const float* ln1_b  = (const float*)d_in[3];
    const float* Wl     = (const float*)d_in[4];
    const float* bl     = (const float*)d_in[5];
    const float* Wr     = (const float*)d_in[6];
    const float* br     = (const float*)d_in[7];
    const float* att    = (const float*)d_in[8];
    const float* gat_b  = (const float*)d_in[9];
    const float* projW  = (const float*)d_in[10];
    const float* projb  = (const float*)d_in[11];
    const float* ln2_g  = (const float*)d_in[12];
    const float* ln2_b  = (const float*)d_in[13];
    const float* W1     = (const float*)d_in[14];
    const float* b1     = (const float*)d_in[15];
    const float* W2     = (const float*)d_in[16];
    const float* b2     = (const float*)d_in[17];

    const int N = in_sizes[0] / DIM;
    const int E = in_sizes[1] / 2;
    float* x = (float*)d_out;

    cudaFuncSetAttribute(gemm_kernel<0>, cudaFuncAttributeMaxDynamicSharedMemorySize, GEMM_SMEM);
    cudaFuncSetAttribute(gemm_kernel<1>, cudaFuncAttributeMaxDynamicSharedMemorySize, GEMM_SMEM);
    cudaFuncSetAttribute(gemm_kernel<2>, cudaFuncAttributeMaxDynamicSharedMemorySize, GEMM_SMEM);
    cudaFuncSetAttribute(gemm_kernel<3>, cudaFuncAttributeMaxDynamicSharedMemorySize, GEMM_SMEM3);

    void *p_xlr, *p_hhi, *p_hlo, *p_gohi, *p_golo, *p_mhi, *p_mlo, *p_wb, *p_blr;
    cudaGetSymbolAddress(&p_xlr, g_xlr);
    cudaGetSymbolAddress(&p_hhi, g_h_hi);
    cudaGetSymbolAddress(&p_hlo, g_h_lo);
    cudaGetSymbolAddress(&p_gohi, g_go_hi);
    cudaGetSymbolAddress(&p_golo, g_go_lo);
    cudaGetSymbolAddress(&p_mhi, g_mid_hi);
    cudaGetSymbolAddress(&p_mlo, g_mid_lo);
    cudaGetSymbolAddress(&p_wb, g_wb);
    cudaGetSymbolAddress(&p_blr, g_blr);
    float* xlr = (float*)p_xlr;
    uint32_t* hhi = (uint32_t*)p_hhi;
    uint32_t* hlo = (uint32_t*)p_hlo;
    uint32_t* gohi = (uint32_t*)p_gohi;
    uint32_t* golo = (uint32_t*)p_golo;
    uint32_t* mhi = (uint32_t*)p_mhi;
    uint32_t* mlo = (uint32_t*)p_mlo;
    uint32_t* wb = (uint32_t*)p_wb;
    float* blr = (float*)p_blr;

    cudaMemcpyAsync(x, x_in, (size_t)N * DIM * sizeof(float), cudaMemcpyDeviceToDevice);

    const int nb = (N + 1023) / 1024;
    detect_kernel<<<1, 256>>>(edges, E, N);
    clear_deg_kernel<<<(N + 255) / 256, 256>>>(N);
    decode_hist_kernel<<<(E + 255) / 256, 256>>>(edges, E);
    scanA_kernel<<<nb, 1024>>>(N);
    scanB_kernel<<<1, 32>>>(nb);
    scanC_kernel<<<(N + 255) / 256, 256>>>(N);
    scatter_kernel<<<(E + 255) / 256, 256>>>(E);

    wconv_all_kernel<<<(2 * LWORDS + 255) / 256, 256>>>(Wl, Wr, projW, W1, W2);
    bconcat_kernel<<<4, 256>>>(bl, br);

    const int ln_blocks = (N + 7) / 8;
    const int mtiles = (N + 127) / 128;

    ln_kernel<<<ln_blocks, 256>>>(x, ln1_g, ln1_b, hhi, hlo, N);

    for (int l = 0; l < 2; l++) {
        size_t off = (size_t)l * LWORDS;
        const uint32_t* wlr = wb + off;
        const uint32_t* pj  = wb + off + 32768;
        const uint32_t* w1  = wb + off + 49152;
        const uint32_t* w2  = wb + off + 81920;
        const float* at_l = att + (size_t)l * HD;
        const float* gb_l = gat_b + (size_t)l * HD;
        const float* pb_l = projb + (size_t)l * DIM;
        const float* b1_l = b1 + (size_t)l * MLPD;
        const float* b2_l = b2 + (size_t)l * DIM;

        gemm_kernel<0><<<pgrid(4 * mtiles), 256, GEMM_SMEM>>>(
            hhi, hlo, wlr, blr + (size_t)l * 512, xlr, nullptr, nullptr,
            nullptr, nullptr, N, DIM, 512);
        gat_node_kernel<<<(N + 7) / 8, 256>>>(xlr, at_l, gb_l, gohi, golo, N);
        gemm_kernel<3><<<pgrid(mtiles), 256, GEMM_SMEM3>>>(
            gohi, golo, pj, pb_l, x, hhi, hlo,
            ln2_g + (size_t)l * DIM, ln2_b + (size_t)l * DIM, N, HD, DIM);
        gemm_kernel<2><<<pgrid(4 * mtiles), 256, GEMM_SMEM>>>(
            hhi, hlo, w1, b1_l, nullptr, mhi, mlo,
            nullptr, nullptr, N, DIM, MLPD);
        if (l == 0) {
            gemm_kernel<3><<<pgrid(mtiles), 256, GEMM_SMEM3>>>(
                mhi, mlo, w2, b2_l, x, hhi, hlo,
                ln1_g + DIM, ln1_b + DIM, N, MLPD, DIM);
        } else {
            gemm_kernel<1><<<pgrid(mtiles), 256, GEMM_SMEM>>>(
                mhi, mlo, w2, b2_l, x, nullptr, nullptr,
                nullptr, nullptr, N, MLPD, DIM);
        }
    }
}

// round 15
// speedup vs baseline: 1.1611x; 1.0910x over previous
#include <cuda_runtime.h>
#include <cuda_fp16.h>
#include <math.h>
#include <stdint.h>

// ----------------------------------------------------------------------------
// GATv2 Transformer. GEMMs: fp16 mma.sync, A split hi+lo (except mid: single
// fp16), weights fp16, cp.async double buffer, persistent CTAs + cross-tile
// prefetch, LN fused into N=128 epilogues. Edge: CSR + online softmax.
// ----------------------------------------------------------------------------

#define MAXN 50000
#define MAXE 800000
#define DIM 128
#define HD 256
#define MLPD 512
#define LWORDS 114688
#define PERSIST_BLOCKS 296     // 148 SMs x 2 CTAs

// ------------------------- scratch (device globals) -------------------------
__device__ __align__(256) float    g_xlr [(size_t)MAXN * 512];
__device__ __align__(256) uint32_t g_h_hi [(size_t)MAXN * (DIM/2)];
__device__ __align__(256) uint32_t g_h_lo [(size_t)MAXN * (DIM/2)];
__device__ __align__(256) uint32_t g_go_hi[(size_t)MAXN * (HD/2)];
__device__ __align__(256) uint32_t g_go_lo[(size_t)MAXN * (HD/2)];
__device__ __align__(256) uint32_t g_mid_hi[(size_t)MAXN * (MLPD/2)];
__device__ __align__(256) uint32_t g_wb[2 * LWORDS];
__device__ __align__(256) float    g_blr[2 * 512];
// CSR
__device__ __align__(256) int g_src[MAXE];
__device__ __align__(256) int g_dst[MAXE];
__device__ __align__(256) int g_esrc[MAXE];
__device__ __align__(256) int g_deg[MAXN];
__device__ __align__(256) int g_off[MAXN + 1];
__device__ __align__(256) int g_pos[MAXN];
__device__ __align__(256) int g_bsum[64];
__device__ __align__(256) int g_boff[64];
__device__ int g_is64;

// ------------------------- helpers -------------------------
__device__ __forceinline__ void split_pack(float x, float y, uint32_t& hi, uint32_t& lo) {
    __half hx = __float2half_rn(x);
    __half hy = __float2half_rn(y);
    __half lx = __float2half_rn(x - __half2float(hx));
    __half ly = __float2half_rn(y - __half2float(hy));
    hi = ((uint32_t)__half_as_ushort(hy) << 16) | (uint32_t)__half_as_ushort(hx);
    lo = ((uint32_t)__half_as_ushort(ly) << 16) | (uint32_t)__half_as_ushort(lx);
}
__device__ __forceinline__ uint32_t pack_h(float x, float y) {
    return ((uint32_t)__half_as_ushort(__float2half_rn(y)) << 16)
         | (uint32_t)__half_as_ushort(__float2half_rn(x));
}
__device__ __forceinline__ float fast_gelu(float u) {
    float z2 = 1.5957691216057308f * (u + 0.044715f * u * u * u);
    return u * __fdividef(1.0f, 1.0f + __expf(-z2));
}

// ------------------------- edge dtype detect / decode+hist -------------------
__global__ void detect_kernel(const void* edges, int E, int N) {
    __shared__ int bad;
    if (threadIdx.x == 0) bad = 0;
    __syncthreads();
    const long long* p = (const long long*)edges;
    int n = E < 2048 ? E : 2048;
    for (int i = threadIdx.x; i < n; i += blockDim.x) {
        long long v = p[i];
        if (v < 0 || v >= (long long)N) atomicOr(&bad, 1);
    }
    __syncthreads();
    if (threadIdx.x == 0) g_is64 = bad ? 0 : 1;
}

__global__ void clear_deg_kernel(int N) {
    int i = blockIdx.x * blockDim.x + threadIdx.x;
    if (i < N) g_deg[i] = 0;
}

__global__ void decode_hist_kernel(const void* edges, int E) {
    int i = blockIdx.x * blockDim.x + threadIdx.x;
    if (i >= E) return;
    int s, d;
    if (g_is64) {
        const long long* p = (const long long*)edges;
        s = (int)p[i];
        d = (int)p[(size_t)E + i];
    } else {
        const int* p = (const int*)edges;
        s = p[i];
        d = p[(size_t)E + i];
    }
    g_src[i] = s;
    g_dst[i] = d;
    atomicAdd(&g_deg[d], 1);
}

// ---- 3-phase parallel scan ----
__global__ void scanA_kernel(int N) {
    int t = threadIdx.x;
    int i = blockIdx.x * 1024 + t;
    int lane = t & 31, w = t >> 5;
    int v = (i < N) ? g_deg[i] : 0;
    int s = v;
    #pragma unroll
    for (int o = 1; o < 32; o <<= 1) {
        int u = __shfl_up_sync(0xffffffffu, s, o);
        if (lane >= o) s += u;
    }
    __shared__ int wt[32];
    if (lane == 31) wt[w] = s;
    __syncthreads();
    if (w == 0) {
        int x = wt[lane];
        #pragma unroll
        for (int o = 1; o < 32; o <<= 1) {
            int u = __shfl_up_sync(0xffffffffu, x, o);
            if (lane >= o) x += u;
        }
        wt[lane] = x;
    }
    __syncthreads();
    if (w) s += wt[w - 1];
    if (i < N) g_off[i + 1] = s;
    if (t == 1023) g_bsum[blockIdx.x] = s;
}

__global__ void scanB_kernel(int nb) {
    int lane = threadIdx.x;
    int v0 = (lane < nb) ? g_bsum[lane] : 0;
    int v1 = (32 + lane < nb) ? g_bsum[32 + lane] : 0;
    int s0 = v0;
    #pragma unroll
    for (int o = 1; o < 32; o <<= 1) {
        int u = __shfl_up_sync(0xffffffffu, s0, o);
        if (lane >= o) s0 += u;
    }
    int tot0 = __shfl_sync(0xffffffffu, s0, 31);
    int s1 = v1;
    #pragma unroll
    for (int o = 1; o < 32; o <<= 1) {
        int u = __shfl_up_sync(0xffffffffu, s1, o);
        if (lane >= o) s1 += u;
    }
    if (lane < nb) g_boff[lane] = s0 - v0;
    if (32 + lane < nb) g_boff[32 + lane] = tot0 + s1 - v1;
}

__global__ void scanC_kernel(int N) {
    int i = blockIdx.x * blockDim.x + threadIdx.x;
    if (i == 0) g_off[0] = 0;
    if (i >= N) return;
    int b = i >> 10;
    int inc = g_off[i + 1] + g_boff[b];
    g_off[i + 1] = inc;
    g_pos[i] = inc - g_deg[i];
}

__global__ void scatter_kernel(int E) {
    int i = blockIdx.x * blockDim.x + threadIdx.x;
    if (i >= E) return;
    int p = atomicAdd(&g_pos[g_dst[i]], 1);
    g_esrc[p] = g_src[i];
}

// ---------------- fused weight convert (single fp16) -------------------------
__global__ void wconv_all_kernel(const float* __restrict__ Wl, const float* __restrict__ Wr,
                                 const float* __restrict__ pj, const float* __restrict__ W1,
                                 const float* __restrict__ W2) {
    int idx = blockIdx.x * blockDim.x + threadIdx.x;
    if (idx >= 2 * LWORDS) return;
    int layer = idx / LWORDS;
    int r = idx - layer * LWORDS;
    const float* W; int K, N;
    if (r < 16384)      { W = Wl + (size_t)layer * 32768; K = 128; N = 256; }
    else if (r < 32768) { W = Wr + (size_t)layer * 32768; r -= 16384; K = 128; N = 256; }
    else if (r < 49152) { W = pj + (size_t)layer * 32768; r -= 32768; K = 256; N = 128; }
    else if (r < 81920) { W = W1 + (size_t)layer * 65536; r -= 49152; K = 128; N = 512; }
    else                { W = W2 + (size_t)layer * 65536; r -= 81920; K = 512; N = 128; }
    int kw = K >> 1;
    int n = r / kw, kp = r - n * kw;
    float x = W[(size_t)(2 * kp) * N + n];
    float y = W[(size_t)(2 * kp + 1) * N + n];
    g_wb[idx] = pack_h(x, y);
}

__global__ void bconcat_kernel(const float* __restrict__ bl, const float* __restrict__ br) {
    int i = threadIdx.x + blockIdx.x * blockDim.x;
    if (i >= 1024) return;
    int layer = i >> 9, j = i & 511;
    float v = (j < 256) ? bl[layer * HD + j] : br[layer * HD + j - 256];
    g_blr[layer * 512 + j] = v;
}

// ------------------------- standalone layernorm ------------------------------
__global__ void ln_kernel(const float* __restrict__ x, const float* __restrict__ g,
                          const float* __restrict__ b,
                          uint32_t* __restrict__ ohi, uint32_t* __restrict__ olo, int N) {
    int row = (blockIdx.x * blockDim.x + threadIdx.x) >> 5;
    int lane = threadIdx.x & 31;
    if (row >= N) return;
    const float4* xr = (const float4*)x + (size_t)row * 32;
    float4 v = xr[lane];
    float s  = v.x + v.y + v.z + v.w;
    float sq = v.x*v.x + v.y*v.y + v.z*v.z + v.w*v.w;
    #pragma unroll
    for (int o = 16; o; o >>= 1) {
        s  += __shfl_xor_sync(0xffffffffu, s,  o);
        sq += __shfl_xor_sync(0xffffffffu, sq, o);
    }
    float m   = s * (1.0f / 128.0f);
    float var = sq * (1.0f / 128.0f) - m * m;
    float inv = rsqrtf(var + 1e-5f);
    float4 gg = ((const float4*)g)[lane];
    float4 bb = ((const float4*)b)[lane];
    float o0 = (v.x - m) * inv * gg.x + bb.x;
    float o1 = (v.y - m) * inv * gg.y + bb.y;
    float o2 = (v.z - m) * inv * gg.z + bb.z;
    float o3 = (v.w - m) * inv * gg.w + bb.w;
    uint32_t h0, l0, h1, l1;
    split_pack(o0, o1, h0, l0);
    split_pack(o2, o3, h1, l1);
    size_t base = (size_t)row * 64 + lane * 2;
    ohi[base] = h0; ohi[base + 1] = h1;
    olo[base] = l0; olo[base + 1] = l1;
}

// ------------------------- tensor-core GEMM --------------------------------
__device__ __forceinline__ void mma16816(float* c, const uint32_t* a, const uint32_t* b) {
    asm volatile(
        "mma.sync.aligned.m16n8k16.row.col.f32.f16.f16.f32 "
        "{%0,%1,%2,%3}, {%4,%5,%6,%7}, {%8,%9}, {%0,%1,%2,%3};"
        : "+f"(c[0]), "+f"(c[1]), "+f"(c[2]), "+f"(c[3])
        : "r"(a[0]), "r"(a[1]), "r"(a[2]), "r"(a[3]), "r"(b[0]), "r"(b[1]));
}

__device__ __forceinline__ void cpa16(uint32_t dst, const void* src, int bytes) {
    asm volatile("cp.async.cg.shared.global [%0], [%1], 16, %2;\n"
                 :: "r"(dst), "l"(src), "r"(bytes));
}

__device__ __forceinline__ int swz(int row, int kp) {
    return (row << 4) | (((kp >> 2) ^ ((row >> 1) & 3)) << 2) | (kp & 3);
}

#define TILE_WORDS 2048
#define BUF_WORDS  (3 * TILE_WORDS)
#define GEMM_SMEM  (2 * BUF_WORDS * 4)       // 48 KB
#define GEMM_SMEM3 65536                     // MODE 3 rowbuf

// MODE 0: store fp32; 1: accumulate fp32; 2: GELU -> single fp16 out;
// MODE 3: accumulate + fused LayerNorm -> writes x (C) and split h (N==128)
// ASPLIT=1: A is hi+lo (2 MMA streams); ASPLIT=0: A single fp16 (1 stream).
// Persistent blocks; next tile's k0 prefetched across the epilogue.
template<int MODE, int ASPLIT>
__global__ __launch_bounds__(256, 2)
void gemm_kernel(const uint32_t* __restrict__ Ahi, const uint32_t* __restrict__ Alo,
                 const uint32_t* __restrict__ Bh_g,
                 const float* __restrict__ bias, float* __restrict__ C,
                 uint32_t* __restrict__ Chi, uint32_t* __restrict__ Clo,
                 const float* __restrict__ lng, const float* __restrict__ lnb,
                 int M, int K, int N) {
    extern __shared__ uint32_t sm[];

    const int tid  = threadIdx.x;
    const int lane = tid & 31;
    const int wid  = tid >> 5;
    const int warp_m = wid & 3;
    const int warp_n = wid >> 2;
    const int g  = lane >> 2;
    const int tg = lane & 3;
    const int kw = K >> 1;
    const int nk = K >> 5;                 // even for all K used (4, 8, 16)
    const int nx = N >> 7;
    const int ntiles = nx * ((M + 127) >> 7);

    const uint32_t sbase = (uint32_t)__cvta_generic_to_shared(sm);

    auto issue = [&](int t, int kt, int b) {
        const int n0_ = (t % nx) * 128;
        const int m0_ = (t / nx) * 128;
        uint32_t bufb = sbase + (uint32_t)(b * BUF_WORDS) * 4;
        #pragma unroll
        for (int q = 0; q < 2; q++) {
            int chunk = tid + q * 256;
            int row = chunk >> 2, c = chunk & 3;
            int dstw = (row << 4) | ((c ^ ((row >> 1) & 3)) << 2);
            int asz = (m0_ + row < M) ? 16 : 0;
            const uint32_t* asrc = Ahi + (size_t)(m0_ + row) * kw + kt * 16 + c * 4;
            const uint32_t* bsrc = Bh_g + (size_t)(n0_ + row) * kw + kt * 16 + c * 4;
            cpa16(bufb + (uint32_t)dstw * 4, asrc, asz);
            if (ASPLIT) {
                const uint32_t* alsr = Alo + (size_t)(m0_ + row) * kw + kt * 16 + c * 4;
                cpa16(bufb + (uint32_t)(TILE_WORDS + dstw) * 4, alsr, asz);
            }
            cpa16(bufb + (uint32_t)(2 * TILE_WORDS + dstw) * 4, bsrc, 16);
        }
        asm volatile("cp.async.commit_group;\n");
    };

    if (blockIdx.x < ntiles) issue(blockIdx.x, 0, 0);

    for (int tile = blockIdx.x; tile < ntiles; tile += gridDim.x) {
        const int n0 = (tile % nx) * 128;
        const int m0 = (tile / nx) * 128;

        float acc[2][8][4];
        #pragma unroll
        for (int i = 0; i < 2; i++)
            #pragma unroll
            for (int j = 0; j < 8; j++)
                #pragma unroll
                for (int r = 0; r < 4; r++) acc[i][j][r] = 0.0f;

        for (int kt = 0; kt < nk; kt++) {
            bool issued;
            if (kt + 1 < nk) {
                issue(tile, kt + 1, (kt + 1) & 1);
                issued = true;
            } else if (MODE != 3 && tile + gridDim.x < ntiles) {
                issue(tile + gridDim.x, 0, 0);   // cross-tile prefetch (nk even)
                issued = true;
            } else {
                issued = false;
            }
            if (issued) { asm volatile("cp.async.wait_group 1;\n"); }
            else        { asm volatile("cp.async.wait_group 0;\n"); }
            __syncthreads();

            const uint32_t* Ah = sm + (kt & 1) * BUF_WORDS;
            const uint32_t* Al = Ah + TILE_WORDS;
            const uint32_t* Bh = Ah + 2 * TILE_WORDS;
            #pragma unroll
            for (int ks = 0; ks < 2; ks++) {
                const int kb = ks * 4;
                uint32_t ah[2][4], al[2][4];
                #pragma unroll
                for (int mt = 0; mt < 2; mt++) {
                    int r0 = warp_m * 32 + mt * 16;
                    ah[mt][0] = Ah[swz(r0 + g,     kb + tg)];
                    ah[mt][1] = Ah[swz(r0 + g + 8, kb + tg)];
                    ah[mt][2] = Ah[swz(r0 + g,     kb + tg + 8)];
                    ah[mt][3] = Ah[swz(r0 + g + 8, kb + tg + 8)];
                    if (ASPLIT) {
                        al[mt][0] = Al[swz(r0 + g,     kb + tg)];
                        al[mt][1] = Al[swz(r0 + g + 8, kb + tg)];
                        al[mt][2] = Al[swz(r0 + g,     kb + tg + 8)];
                        al[mt][3] = Al[swz(r0 + g + 8, kb + tg + 8)];
                    }
                }
                #pragma unroll
                for (int nt = 0; nt < 8; nt++) {
                    int col = warp_n * 64 + nt * 8 + g;
                    uint32_t bh[2];
                    bh[0] = Bh[swz(col, kb + tg)];
                    bh[1] = Bh[swz(col, kb + tg + 8)];
                    #pragma unroll
                    for (int mt = 0; mt < 2; mt++) {
                        float* c = acc[mt][nt];
                        mma16816(c, ah[mt], bh);
                        if (ASPLIT) mma16816(c, al[mt], bh);
                    }
                }
            }
            __syncthreads();
        }

        // ---- epilogue (no smem except MODE 3) ----
        float* rowbuf = (float*)sm;
        #pragma unroll
        for (int mt = 0; mt < 2; mt++) {
            int rloc = warp_m * 32 + mt * 16 + (lane >> 2);
            int row = m0 + rloc;
            #pragma unroll
            for (int nt = 0; nt < 8; nt++) {
                int col = n0 + warp_n * 64 + nt * 8 + (lane & 3) * 2;
                float2 bb = *(const float2*)(bias + col);
                #pragma unroll
                for (int half = 0; half < 2; half++) {
                    int r = row + half * 8;
                    if (r >= M) continue;
                    float v0 = acc[mt][nt][2 * half]     + bb.x;
                    float v1 = acc[mt][nt][2 * half + 1] + bb.y;
                    if (MODE == 2) {
                        v0 = fast_gelu(v0);
                        v1 = fast_gelu(v1);
                        Chi[(size_t)r * (N >> 1) + (col >> 1)] = pack_h(v0, v1);
                    } else if (MODE == 3) {
                        float2 old = *(float2*)(C + (size_t)r * N + col);
                        rowbuf[(rloc + half * 8) * 128 + (col - n0)]     = v0 + old.x;
                        rowbuf[(rloc + half * 8) * 128 + (col - n0) + 1] = v1 + old.y;
                    } else {
                        float2* dst = (float2*)(C + (size_t)r * N + col);
                        if (MODE == 1) {
                            float2 old = *dst;
                            v0 += old.x; v1 += old.y;
                        }
                        *dst = make_float2(v0, v1);
                    }
                }
            }
        }

        if (MODE == 3) {
            __syncthreads();
            float4 gg = ((const float4*)lng)[lane];
            float4 bb2 = ((const float4*)lnb)[lane];
            for (int rr = wid * 16; rr < wid * 16 + 16; rr++) {
                int r = m0 + rr;
                if (r >= M) break;
                float4 v = ((const float4*)(rowbuf + rr * 128))[lane];
                float s  = v.x + v.y + v.z + v.w;
                float sq = v.x*v.x + v.y*v.y + v.z*v.z + v.w*v.w;
                #pragma unroll
                for (int o = 16; o; o >>= 1) {
                    s  += __shfl_xor_sync(0xffffffffu, s,  o);
                    sq += __shfl_xor_sync(0xffffffffu, sq, o);
                }
                float m   = s * (1.0f / 128.0f);
                float var = sq * (1.0f / 128.0f) - m * m;
                float inv = rsqrtf(var + 1e-5f);
                ((float4*)(C + (size_t)r * 128))[lane] = v;
                float o0 = (v.x - m) * inv * gg.x + bb2.x;
                float o1 = (v.y - m) * inv * gg.y + bb2.y;
                float o2 = (v.z - m) * inv * gg.z + bb2.z;
                float o3 = (v.w - m) * inv * gg.w + bb2.w;
                uint32_t h0, l0, h1, l1;
                split_pack(o0, o1, h0, l0);
                split_pack(o2, o3, h1, l1);
                size_t base = (size_t)r * 64 + lane * 2;
                Chi[base] = h0; Chi[base + 1] = h1;
                Clo[base] = l0; Clo[base + 1] = l1;
            }
            __syncthreads();   // rowbuf reads done -> buffers reusable
            if (tile + gridDim.x < ntiles)
                issue(tile + gridDim.x, 0, 0);   // MODE 3 seeds its next tile here
        }
    }
}

// ------------------- fused GATv2 node kernel (warp per dst) ------------------
__global__ void gat_node_kernel(const float* __restrict__ xlr,
                                const float* __restrict__ att,
                                const float* __restrict__ gat_b,
                                uint32_t* __restrict__ gohi, uint32_t* __restrict__ golo,
                                int N) {
    int node = (blockIdx.x * blockDim.x + threadIdx.x) >> 5;
    int lane = threadIdx.x & 31;
    if (node >= N) return;

    const float4* base = (const float4*)xlr;
    float4 r0 = base[(size_t)node * 128 + 64 + lane];
    float4 r1 = base[(size_t)node * 128 + 96 + lane];
    float4 a0 = ((const float4*)att)[lane];
    float4 a1 = ((const float4*)att)[32 + lane];

    float mA0 = -1e30f, mA1 = -1e30f, dA0 = 0.f, dA1 = 0.f;
    float mB0 = -1e30f, mB1 = -1e30f, dB0 = 0.f, dB1 = 0.f;
    float4 aA0 = make_float4(0.f,0.f,0.f,0.f), aA1 = make_float4(0.f,0.f,0.f,0.f);
    float4 aB0 = make_float4(0.f,0.f,0.f,0.f), aB1 = make_float4(0.f,0.f,0.f,0.f);

    int beg = g_off[node], end = g_off[node + 1];

    auto process = [&](int s, float& m0, float& m1, float& d0, float& d1,
                       float4& acc0, float4& acc1) {
        float4 l0 = base[(size_t)s * 128 + lane];
        float4 l1 = base[(size_t)s * 128 + 32 + lane];
        float4 e0, e1;
        e0.x = l0.x + r0.x; e0.x = e0.x > 0.f ? e0.x : 0.2f * e0.x;
        e0.y = l0.y + r0.y; e0.y = e0.y > 0.f ? e0.y : 0.2f * e0.y;
        e0.z = l0.z + r0.z; e0.z = e0.z > 0.f ? e0.z : 0.2f * e0.z;
        e0.w = l0.w + r0.w; e0.w = e0.w > 0.f ? e0.w : 0.2f * e0.w;
        e1.x = l1.x + r1.x; e1.x = e1.x > 0.f ? e1.x : 0.2f * e1.x;
        e1.y = l1.y + r1.y; e1.y = e1.y > 0.f ? e1.y : 0.2f * e1.y;
        e1.z = l1.z + r1.z; e1.z = e1.z > 0.f ? e1.z : 0.2f * e1.z;
        e1.w = l1.w + r1.w; e1.w = e1.w > 0.f ? e1.w : 0.2f * e1.w;
        float p0 = e0.x * a0.x + e0.y * a0.y + e0.z * a0.z + e0.w * a0.w;
        float p1 = e1.x * a1.x + e1.y * a1.y + e1.z * a1.z + e1.w * a1.w;
        #pragma unroll
        for (int o = 16; o; o >>= 1) {
            p0 += __shfl_xor_sync(0xffffffffu, p0, o);
            p1 += __shfl_xor_sync(0xffffffffu, p1, o);
        }
        float nm0 = fmaxf(m0, p0);
        float f0 = __expf(m0 - nm0);
        float w0 = __expf(p0 - nm0);
        m0 = nm0;
        d0 = d0 * f0 + w0;
        acc0.x = acc0.x * f0 + w0 * l0.x;
        acc0.y = acc0.y * f0 + w0 * l0.y;
        acc0.z = acc0.z * f0 + w0 * l0.z;
        acc0.w = acc0.w * f0 + w0 * l0.w;
        float nm1 = fmaxf(m1, p1);
        float f1 = __expf(m1 - nm1);
        float w1 = __expf(p1 - nm1);
        m1 = nm1;
        d1 = d1 * f1 + w1;
        acc1.x = acc1.x * f1 + w1 * l1.x;
        acc1.y = acc1.y * f1 + w1 * l1.y;
        acc1.z = acc1.z * f1 + w1 * l1.z;
        acc1.w = acc1.w * f1 + w1 * l1.w;
    };

    int i = beg;
    for (; i + 1 < end; i += 2) {
        int sA = g_esrc[i];
        int sB = g_esrc[i + 1];
        process(sA, mA0, mA1, dA0, dA1, aA0, aA1);
        process(sB, mB0, mB1, dB0, dB1, aB0, aB1);
    }
    if (i < end) process(g_esrc[i], mA0, mA1, dA0, dA1, aA0, aA1);

    {
        float m = fmaxf(mA0, mB0);
        float fA = __expf(mA0 - m), fB = __expf(mB0 - m);
        dA0 = dA0 * fA + dB0 * fB;
        aA0.x = aA0.x * fA + aB0.x * fB;
        aA0.y = aA0.y * fA + aB0.y * fB;
        aA0.z = aA0.z * fA + aB0.z * fB;
        aA0.w = aA0.w * fA + aB0.w * fB;
        m = fmaxf(mA1, mB1);
        fA = __expf(mA1 - m); fB = __expf(mB1 - m);
        dA1 = dA1 * fA + dB1 * fB;
        aA1.x = aA1.x * fA + aB1.x * fB;
        aA1.y = aA1.y * fA + aB1.y * fB;
        aA1.z = aA1.z * fA + aB1.z * fB;
        aA1.w = aA1.w * fA + aB1.w * fB;
    }

    float inv0 = 1.0f / (dA0 + 1e-16f);
    float inv1 = 1.0f / (dA1 + 1e-16f);
    const float4* gb4 = (const float4*)gat_b;
    float4 b0 = gb4[lane];
    float4 b1 = gb4[32 + lane];
    float o0 = aA0.x * inv0 + b0.x, o1 = aA0.y * inv0 + b0.y;
    float o2 = aA0.z * inv0 + b0.z, o3 = aA0.w * inv0 + b0.w;
    float o4 = aA1.x * inv1 + b1.x, o5 = aA1.y * inv1 + b1.y;
    float o6 = aA1.z * inv1 + b1.z, o7 = aA1.w * inv1 + b1.w;

    uint32_t h0, l0w, h1, l1w, h2, l2w, h3, l3w;
    split_pack(o0, o1, h0, l0w);
    split_pack(o2, o3, h1, l1w);
    split_pack(o4, o5, h2, l2w);
    split_pack(o6, o7, h3, l3w);
    size_t rb = (size_t)node * 128;
    gohi[rb + lane * 2]          = h0;  golo[rb + lane * 2]          = l0w;
    gohi[rb + lane * 2 + 1]      = h1;  golo[rb + lane * 2 + 1]      = l1w;
    gohi[rb + 64 + lane * 2]     = h2;  golo[rb + 64 + lane * 2]     = l2w;
    gohi[rb + 64 + lane * 2 + 1] = h3;  golo[rb + 64 + lane * 2 + 1] = l3w;
}

// ------------------------- launch --------------------------------------------
static inline int pgrid(int ntiles) { return ntiles < PERSIST_BLOCKS ? ntiles : PERSIST_BLOCKS; }

extern "C" void kernel_launch(void* const* d_in, const int* in_sizes, int n_in,
                              void* d_out, int out_size) {
    const float* x_in   = (const float*)d_in[0];
    const void*  edges  = d_in[1];
    const float* ln1_g  = (const float*)d_in[2];
    const float* ln1_b  = (const float*)d_in[3];
    const float* Wl     = (const float*)d_in[4];
    const float* bl     = (const float*)d_in[5];
    const float* Wr     = (const float*)d_in[6];
    const float* br     = (const float*)d_in[7];
    const float* att    = (const float*)d_in[8];
    const float* gat_b  = (const float*)d_in[9];
    const float* projW  = (const float*)d_in[10];
    const float* projb  = (const float*)d_in[11];
    const float* ln2_g  = (const float*)d_in[12];
    const float* ln2_b  = (const float*)d_in[13];
    const float* W1     = (const float*)d_in[14];
    const float* b1     = (const float*)d_in[15];
    const float* W2     = (const float*)d_in[16];
    const float* b2     = (const float*)d_in[17];

    const int N = in_sizes[0] / DIM;
    const int E = in_sizes[1] / 2;
    float* x = (float*)d_out;

    cudaFuncSetAttribute(gemm_kernel<0,1>, cudaFuncAttributeMaxDynamicSharedMemorySize, GEMM_SMEM);
    cudaFuncSetAttribute(gemm_kernel<1,0>, cudaFuncAttributeMaxDynamicSharedMemorySize, GEMM_SMEM);
    cudaFuncSetAttribute(gemm_kernel<2,1>, cudaFuncAttributeMaxDynamicSharedMemorySize, GEMM_SMEM);
    cudaFuncSetAttribute(gemm_kernel<3,1>, cudaFuncAttributeMaxDynamicSharedMemorySize, GEMM_SMEM3);
    cudaFuncSetAttribute(gemm_kernel<3,0>, cudaFuncAttributeMaxDynamicSharedMemorySize, GEMM_SMEM3);

    void *p_xlr, *p_hhi, *p_hlo, *p_gohi, *p_golo, *p_mhi, *p_wb, *p_blr;
    cudaGetSymbolAddress(&p_xlr, g_xlr);
    cudaGetSymbolAddress(&p_hhi, g_h_hi);
    cudaGetSymbolAddress(&p_hlo, g_h_lo);
    cudaGetSymbolAddress(&p_gohi, g_go_hi);
    cudaGetSymbolAddress(&p_golo, g_go_lo);
    cudaGetSymbolAddress(&p_mhi, g_mid_hi);
    cudaGetSymbolAddress(&p_wb, g_wb);
    cudaGetSymbolAddress(&p_blr, g_blr);
    float* xlr = (float*)p_xlr;
    uint32_t* hhi = (uint32_t*)p_hhi;
    uint32_t* hlo = (uint32_t*)p_hlo;
    uint32_t* gohi = (uint32_t*)p_gohi;
    uint32_t* golo = (uint32_t*)p_golo;
    uint32_t* mhi = (uint32_t*)p_mhi;
    uint32_t* wb = (uint32_t*)p_wb;
    float* blr = (float*)p_blr;

    cudaMemcpyAsync(x, x_in, (size_t)N * DIM * sizeof(float), cudaMemcpyDeviceToDevice);

    const int nb = (N + 1023) / 1024;
    detect_kernel<<<1, 256>>>(edges, E, N);
    clear_deg_kernel<<<(N + 255) / 256, 256>>>(N);
    decode_hist_kernel<<<(E + 255) / 256, 256>>>(edges, E);
    scanA_kernel<<<nb, 1024>>>(N);
    scanB_kernel<<<1, 32>>>(nb);
    scanC_kernel<<<(N + 255) / 256, 256>>>(N);
    scatter_kernel<<<(E + 255) / 256, 256>>>(E);

    wconv_all_kernel<<<(2 * LWORDS + 255) / 256, 256>>>(Wl, Wr, projW, W1, W2);
    bconcat_kernel<<<4, 256>>>(bl, br);

    const int ln_blocks = (N + 7) / 8;
    const int mtiles = (N + 127) / 128;

    ln_kernel<<<ln_blocks, 256>>>(x, ln1_g, ln1_b, hhi, hlo, N);

    for (int l = 0; l < 2; l++) {
        size_t off = (size_t)l * LWORDS;
        const uint32_t* wlr = wb + off;
        const uint32_t* pj  = wb + off + 32768;
        const uint32_t* w1  = wb + off + 49152;
        const uint32_t* w2  = wb + off + 81920;
        const float* at_l = att + (size_t)l * HD;
        const float* gb_l = gat_b + (size_t)l * HD;
        const float* pb_l = projb + (size_t)l * DIM;
        const float* b1_l = b1 + (size_t)l * MLPD;
        const float* b2_l = b2 + (size_t)l * DIM;

        gemm_kernel<0,1><<<pgrid(4 * mtiles), 256, GEMM_SMEM>>>(
            hhi, hlo, wlr, blr + (size_t)l * 512, xlr, nullptr, nullptr,
            nullptr, nullptr, N, DIM, 512);
        gat_node_kernel<<<(N + 7) / 8, 256>>>(xlr, at_l, gb_l, gohi, golo, N);
        gemm_kernel<3,1><<<pgrid(mtiles), 256, GEMM_SMEM3>>>(
            gohi, golo, pj, pb_l, x, hhi, hlo,
            ln2_g + (size_t)l * DIM, ln2_b + (size_t)l * DIM, N, HD, DIM);
        // mid = gelu(h @ W1 + b1) -> single fp16
        gemm_kernel<2,1><<<pgrid(4 * mtiles), 256, GEMM_SMEM>>>(
            hhi, hlo, w1, b1_l, nullptr, mhi, nullptr,
            nullptr, nullptr, N, DIM, MLPD);
        // x += mid @ W2 + b2 (A single fp16)
        if (l == 0) {
            gemm_kernel<3,0><<<pgrid(mtiles), 256, GEMM_SMEM3>>>(
                mhi, mhi, w2, b2_l, x, hhi, hlo,
                ln1_g + DIM, ln1_b + DIM, N, MLPD, DIM);
        } else {
            gemm_kernel<1,0><<<pgrid(mtiles), 256, GEMM_SMEM>>>(
                mhi, mhi, w2, b2_l, x, nullptr, nullptr,
                nullptr, nullptr, N, MLPD, DIM);
        }
    }
}

// round 16
// speedup vs baseline: 1.3530x; 1.1654x over previous
#include <cuda_runtime.h>
#include <cuda_fp16.h>
#include <math.h>
#include <stdint.h>

// ----------------------------------------------------------------------------
// GATv2 Transformer. GEMMs: fp16 mma.sync, ALL operands single fp16,
// cp.async double buffer, persistent CTAs + cross-tile prefetch, LN fused
// into N=128 epilogues. Edge: CSR + dual-state online softmax (fp32 xlr).
// ----------------------------------------------------------------------------

#define MAXN 50000
#define MAXE 800000
#define DIM 128
#define HD 256
#define MLPD 512
#define LWORDS 114688
#define PERSIST_BLOCKS 296     // 148 SMs x 2 CTAs

// ------------------------- scratch (device globals) -------------------------
__device__ __align__(256) float    g_xlr [(size_t)MAXN * 512];
__device__ __align__(256) uint32_t g_h   [(size_t)MAXN * (DIM/2)];
__device__ __align__(256) uint32_t g_go  [(size_t)MAXN * (HD/2)];
__device__ __align__(256) uint32_t g_mid [(size_t)MAXN * (MLPD/2)];
__device__ __align__(256) uint32_t g_wb[2 * LWORDS];
__device__ __align__(256) float    g_blr[2 * 512];
// CSR
__device__ __align__(256) int g_src[MAXE];
__device__ __align__(256) int g_dst[MAXE];
__device__ __align__(256) int g_esrc[MAXE];
__device__ __align__(256) int g_deg[MAXN];
__device__ __align__(256) int g_off[MAXN + 1];
__device__ __align__(256) int g_pos[MAXN];
__device__ __align__(256) int g_bsum[64];
__device__ __align__(256) int g_boff[64];
__device__ int g_is64;

// ------------------------- helpers -------------------------
__device__ __forceinline__ uint32_t pack_h(float x, float y) {
    return ((uint32_t)__half_as_ushort(__float2half_rn(y)) << 16)
         | (uint32_t)__half_as_ushort(__float2half_rn(x));
}
__device__ __forceinline__ float fast_gelu(float u) {
    float z2 = 1.5957691216057308f * (u + 0.044715f * u * u * u);
    return u * __fdividef(1.0f, 1.0f + __expf(-z2));
}

// ------------------------- edge dtype detect / decode+hist -------------------
__global__ void detect_kernel(const void* edges, int E, int N) {
    __shared__ int bad;
    if (threadIdx.x == 0) bad = 0;
    __syncthreads();
    const long long* p = (const long long*)edges;
    int n = E < 2048 ? E : 2048;
    for (int i = threadIdx.x; i < n; i += blockDim.x) {
        long long v = p[i];
        if (v < 0 || v >= (long long)N) atomicOr(&bad, 1);
    }
    __syncthreads();
    if (threadIdx.x == 0) g_is64 = bad ? 0 : 1;
}

__global__ void clear_deg_kernel(int N) {
    int i = blockIdx.x * blockDim.x + threadIdx.x;
    if (i < N) g_deg[i] = 0;
}

__global__ void decode_hist_kernel(const void* edges, int E) {
    int i = blockIdx.x * blockDim.x + threadIdx.x;
    if (i >= E) return;
    int s, d;
    if (g_is64) {
        const long long* p = (const long long*)edges;
        s = (int)p[i];
        d = (int)p[(size_t)E + i];
    } else {
        const int* p = (const int*)edges;
        s = p[i];
        d = p[(size_t)E + i];
    }
    g_src[i] = s;
    g_dst[i] = d;
    atomicAdd(&g_deg[d], 1);
}

// ---- 3-phase parallel scan ----
__global__ void scanA_kernel(int N) {
    int t = threadIdx.x;
    int i = blockIdx.x * 1024 + t;
    int lane = t & 31, w = t >> 5;
    int v = (i < N) ? g_deg[i] : 0;
    int s = v;
    #pragma unroll
    for (int o = 1; o < 32; o <<= 1) {
        int u = __shfl_up_sync(0xffffffffu, s, o);
        if (lane >= o) s += u;
    }
    __shared__ int wt[32];
    if (lane == 31) wt[w] = s;
    __syncthreads();
    if (w == 0) {
        int x = wt[lane];
        #pragma unroll
        for (int o = 1; o < 32; o <<= 1) {
            int u = __shfl_up_sync(0xffffffffu, x, o);
            if (lane >= o) x += u;
        }
        wt[lane] = x;
    }
    __syncthreads();
    if (w) s += wt[w - 1];
    if (i < N) g_off[i + 1] = s;
    if (t == 1023) g_bsum[blockIdx.x] = s;
}

__global__ void scanB_kernel(int nb) {
    int lane = threadIdx.x;
    int v0 = (lane < nb) ? g_bsum[lane] : 0;
    int v1 = (32 + lane < nb) ? g_bsum[32 + lane] : 0;
    int s0 = v0;
    #pragma unroll
    for (int o = 1; o < 32; o <<= 1) {
        int u = __shfl_up_sync(0xffffffffu, s0, o);
        if (lane >= o) s0 += u;
    }
    int tot0 = __shfl_sync(0xffffffffu, s0, 31);
    int s1 = v1;
    #pragma unroll
    for (int o = 1; o < 32; o <<= 1) {
        int u = __shfl_up_sync(0xffffffffu, s1, o);
        if (lane >= o) s1 += u;
    }
    if (lane < nb) g_boff[lane] = s0 - v0;
    if (32 + lane < nb) g_boff[32 + lane] = tot0 + s1 - v1;
}

__global__ void scanC_kernel(int N) {
    int i = blockIdx.x * blockDim.x + threadIdx.x;
    if (i == 0) g_off[0] = 0;
    if (i >= N) return;
    int b = i >> 10;
    int inc = g_off[i + 1] + g_boff[b];
    g_off[i + 1] = inc;
    g_pos[i] = inc - g_deg[i];
}

__global__ void scatter_kernel(int E) {
    int i = blockIdx.x * blockDim.x + threadIdx.x;
    if (i >= E) return;
    int p = atomicAdd(&g_pos[g_dst[i]], 1);
    g_esrc[p] = g_src[i];
}

// ---------------- fused weight convert (single fp16) -------------------------
__global__ void wconv_all_kernel(const float* __restrict__ Wl, const float* __restrict__ Wr,
                                 const float* __restrict__ pj, const float* __restrict__ W1,
                                 const float* __restrict__ W2) {
    int idx = blockIdx.x * blockDim.x + threadIdx.x;
    if (idx >= 2 * LWORDS) return;
    int layer = idx / LWORDS;
    int r = idx - layer * LWORDS;
    const float* W; int K, N;
    if (r < 16384)      { W = Wl + (size_t)layer * 32768; K = 128; N = 256; }
    else if (r < 32768) { W = Wr + (size_t)layer * 32768; r -= 16384; K = 128; N = 256; }
    else if (r < 49152) { W = pj + (size_t)layer * 32768; r -= 32768; K = 256; N = 128; }
    else if (r < 81920) { W = W1 + (size_t)layer * 65536; r -= 49152; K = 128; N = 512; }
    else                { W = W2 + (size_t)layer * 65536; r -= 81920; K = 512; N = 128; }
    int kw = K >> 1;
    int n = r / kw, kp = r - n * kw;
    float x = W[(size_t)(2 * kp) * N + n];
    float y = W[(size_t)(2 * kp + 1) * N + n];
    g_wb[idx] = pack_h(x, y);
}

__global__ void bconcat_kernel(const float* __restrict__ bl, const float* __restrict__ br) {
    int i = threadIdx.x + blockIdx.x * blockDim.x;
    if (i >= 1024) return;
    int layer = i >> 9, j = i & 511;
    float v = (j < 256) ? bl[layer * HD + j] : br[layer * HD + j - 256];
    g_blr[layer * 512 + j] = v;
}

// ------------------------- standalone layernorm ------------------------------
__global__ void ln_kernel(const float* __restrict__ x, const float* __restrict__ g,
                          const float* __restrict__ b,
                          uint32_t* __restrict__ oh, int N) {
    int row = (blockIdx.x * blockDim.x + threadIdx.x) >> 5;
    int lane = threadIdx.x & 31;
    if (row >= N) return;
    const float4* xr = (const float4*)x + (size_t)row * 32;
    float4 v = xr[lane];
    float s  = v.x + v.y + v.z + v.w;
    float sq = v.x*v.x + v.y*v.y + v.z*v.z + v.w*v.w;
    #pragma unroll
    for (int o = 16; o; o >>= 1) {
        s  += __shfl_xor_sync(0xffffffffu, s,  o);
        sq += __shfl_xor_sync(0xffffffffu, sq, o);
    }
    float m   = s * (1.0f / 128.0f);
    float var = sq * (1.0f / 128.0f) - m * m;
    float inv = rsqrtf(var + 1e-5f);
    float4 gg = ((const float4*)g)[lane];
    float4 bb = ((const float4*)b)[lane];
    float o0 = (v.x - m) * inv * gg.x + bb.x;
    float o1 = (v.y - m) * inv * gg.y + bb.y;
    float o2 = (v.z - m) * inv * gg.z + bb.z;
    float o3 = (v.w - m) * inv * gg.w + bb.w;
    size_t base = (size_t)row * 64 + lane * 2;
    oh[base]     = pack_h(o0, o1);
    oh[base + 1] = pack_h(o2, o3);
}

// ------------------------- tensor-core GEMM --------------------------------
__device__ __forceinline__ void mma16816(float* c, const uint32_t* a, const uint32_t* b) {
    asm volatile(
        "mma.sync.aligned.m16n8k16.row.col.f32.f16.f16.f32 "
        "{%0,%1,%2,%3}, {%4,%5,%6,%7}, {%8,%9}, {%0,%1,%2,%3};"
        : "+f"(c[0]), "+f"(c[1]), "+f"(c[2]), "+f"(c[3])
        : "r"(a[0]), "r"(a[1]), "r"(a[2]), "r"(a[3]), "r"(b[0]), "r"(b[1]));
}

__device__ __forceinline__ void cpa16(uint32_t dst, const void* src, int bytes) {
    asm volatile("cp.async.cg.shared.global [%0], [%1], 16, %2;\n"
                 :: "r"(dst), "l"(src), "r"(bytes));
}

__device__ __forceinline__ int swz(int row, int kp) {
    return (row << 4) | (((kp >> 2) ^ ((row >> 1) & 3)) << 2) | (kp & 3);
}

#define TILE_WORDS 2048
#define BUF_WORDS  (2 * TILE_WORDS)          // A, B
#define GEMM_SMEM  (2 * BUF_WORDS * 4)       // 32 KB
#define GEMM_SMEM3 65536                     // MODE 3 rowbuf

// MODE 0: store fp32; 1: accumulate fp32; 2: GELU -> single fp16 out;
// MODE 3: accumulate + fused LayerNorm -> writes x (C) and fp16 h (N==128)
// Persistent blocks; next tile's k0 prefetched across the epilogue
// (inline for MODE!=3; after the LN epilogue + sync for MODE 3).
template<int MODE>
__global__ __launch_bounds__(256, 2)
void gemm_kernel(const uint32_t* __restrict__ A_g,
                 const uint32_t* __restrict__ Bh_g,
                 const float* __restrict__ bias, float* __restrict__ C,
                 uint32_t* __restrict__ Ch,
                 const float* __restrict__ lng, const float* __restrict__ lnb,
                 int M, int K, int N) {
    extern __shared__ uint32_t sm[];

    const int tid  = threadIdx.x;
    const int lane = tid & 31;
    const int wid  = tid >> 5;
    const int warp_m = wid & 3;
    const int warp_n = wid >> 2;
    const int g  = lane >> 2;
    const int tg = lane & 3;
    const int kw = K >> 1;
    const int nk = K >> 5;                 // even for all K used (4, 8, 16)
    const int nx = N >> 7;
    const int ntiles = nx * ((M + 127) >> 7);

    const uint32_t sbase = (uint32_t)__cvta_generic_to_shared(sm);

    auto issue = [&](int t, int kt, int b) {
        const int n0_ = (t % nx) * 128;
        const int m0_ = (t / nx) * 128;
        uint32_t bufb = sbase + (uint32_t)(b * BUF_WORDS) * 4;
        #pragma unroll
        for (int q = 0; q < 2; q++) {
            int chunk = tid + q * 256;
            int row = chunk >> 2, c = chunk & 3;
            int dstw = (row << 4) | ((c ^ ((row >> 1) & 3)) << 2);
            int asz = (m0_ + row < M) ? 16 : 0;
            const uint32_t* asrc = A_g  + (size_t)(m0_ + row) * kw + kt * 16 + c * 4;
            const uint32_t* bsrc = Bh_g + (size_t)(n0_ + row) * kw + kt * 16 + c * 4;
            cpa16(bufb + (uint32_t)dstw * 4,                 asrc, asz);
            cpa16(bufb + (uint32_t)(TILE_WORDS + dstw) * 4,  bsrc, 16);
        }
        asm volatile("cp.async.commit_group;\n");
    };

    if (blockIdx.x < ntiles) issue(blockIdx.x, 0, 0);

    for (int tile = blockIdx.x; tile < ntiles; tile += gridDim.x) {
        const int n0 = (tile % nx) * 128;
        const int m0 = (tile / nx) * 128;

        float acc[2][8][4];
        #pragma unroll
        for (int i = 0; i < 2; i++)
            #pragma unroll
            for (int j = 0; j < 8; j++)
                #pragma unroll
                for (int r = 0; r < 4; r++) acc[i][j][r] = 0.0f;

        for (int kt = 0; kt < nk; kt++) {
            bool issued;
            if (kt + 1 < nk) {
                issue(tile, kt + 1, (kt + 1) & 1);
                issued = true;
            } else if (MODE != 3 && tile + gridDim.x < ntiles) {
                issue(tile + gridDim.x, 0, 0);   // cross-tile prefetch (nk even)
                issued = true;
            } else {
                issued = false;
            }
            if (issued) { asm volatile("cp.async.wait_group 1;\n"); }
            else        { asm volatile("cp.async.wait_group 0;\n"); }
            __syncthreads();

            const uint32_t* Ah = sm + (kt & 1) * BUF_WORDS;
            const uint32_t* Bh = Ah + TILE_WORDS;
            #pragma unroll
            for (int ks = 0; ks < 2; ks++) {
                const int kb = ks * 4;
                uint32_t ah[2][4];
                #pragma unroll
                for (int mt = 0; mt < 2; mt++) {
                    int r0 = warp_m * 32 + mt * 16;
                    ah[mt][0] = Ah[swz(r0 + g,     kb + tg)];
                    ah[mt][1] = Ah[swz(r0 + g + 8, kb + tg)];
                    ah[mt][2] = Ah[swz(r0 + g,     kb + tg + 8)];
                    ah[mt][3] = Ah[swz(r0 + g + 8, kb + tg + 8)];
                }
                #pragma unroll
                for (int nt = 0; nt < 8; nt++) {
                    int col = warp_n * 64 + nt * 8 + g;
                    uint32_t bh[2];
                    bh[0] = Bh[swz(col, kb + tg)];
                    bh[1] = Bh[swz(col, kb + tg + 8)];
                    #pragma unroll
                    for (int mt = 0; mt < 2; mt++)
                        mma16816(acc[mt][nt], ah[mt], bh);
                }
            }
            __syncthreads();
        }

        // ---- epilogue (no smem except MODE 3) ----
        float* rowbuf = (float*)sm;
        #pragma unroll
        for (int mt = 0; mt < 2; mt++) {
            int rloc = warp_m * 32 + mt * 16 + (lane >> 2);
            int row = m0 + rloc;
            #pragma unroll
            for (int nt = 0; nt < 8; nt++) {
                int col = n0 + warp_n * 64 + nt * 8 + (lane & 3) * 2;
                float2 bb = *(const float2*)(bias + col);
                #pragma unroll
                for (int half = 0; half < 2; half++) {
                    int r = row + half * 8;
                    if (r >= M) continue;
                    float v0 = acc[mt][nt][2 * half]     + bb.x;
                    float v1 = acc[mt][nt][2 * half + 1] + bb.y;
                    if (MODE == 2) {
                        v0 = fast_gelu(v0);
                        v1 = fast_gelu(v1);
                        Ch[(size_t)r * (N >> 1) + (col >> 1)] = pack_h(v0, v1);
                    } else if (MODE == 3) {
                        float2 old = *(float2*)(C + (size_t)r * N + col);
                        rowbuf[(rloc + half * 8) * 128 + (col - n0)]     = v0 + old.x;
                        rowbuf[(rloc + half * 8) * 128 + (col - n0) + 1] = v1 + old.y;
                    } else {
                        float2* dst = (float2*)(C + (size_t)r * N + col);
                        if (MODE == 1) {
                            float2 old = *dst;
                            v0 += old.x; v1 += old.y;
                        }
                        *dst = make_float2(v0, v1);
                    }
                }
            }
        }

        if (MODE == 3) {
            __syncthreads();
            float4 gg = ((const float4*)lng)[lane];
            float4 bb2 = ((const float4*)lnb)[lane];
            for (int rr = wid * 16; rr < wid * 16 + 16; rr++) {
                int r = m0 + rr;
                if (r >= M) break;
                float4 v = ((const float4*)(rowbuf + rr * 128))[lane];
                float s  = v.x + v.y + v.z + v.w;
                float sq = v.x*v.x + v.y*v.y + v.z*v.z + v.w*v.w;
                #pragma unroll
                for (int o = 16; o; o >>= 1) {
                    s  += __shfl_xor_sync(0xffffffffu, s,  o);
                    sq += __shfl_xor_sync(0xffffffffu, sq, o);
                }
                float m   = s * (1.0f / 128.0f);
                float var = sq * (1.0f / 128.0f) - m * m;
                float inv = rsqrtf(var + 1e-5f);
                ((float4*)(C + (size_t)r * 128))[lane] = v;
                float o0 = (v.x - m) * inv * gg.x + bb2.x;
                float o1 = (v.y - m) * inv * gg.y + bb2.y;
                float o2 = (v.z - m) * inv * gg.z + bb2.z;
                float o3 = (v.w - m) * inv * gg.w + bb2.w;
                size_t base = (size_t)r * 64 + lane * 2;
                Ch[base]     = pack_h(o0, o1);
                Ch[base + 1] = pack_h(o2, o3);
            }
            __syncthreads();   // rowbuf reads done -> buffers reusable
            if (tile + gridDim.x < ntiles)
                issue(tile + gridDim.x, 0, 0);   // MODE 3 seeds its next tile here
        }
    }
}

// ------------------- fused GATv2 node kernel (warp per dst) ------------------
__global__ void gat_node_kernel(const float* __restrict__ xlr,
                                const float* __restrict__ att,
                                const float* __restrict__ gat_b,
                                uint32_t* __restrict__ go, int N) {
    int node = (blockIdx.x * blockDim.x + threadIdx.x) >> 5;
    int lane = threadIdx.x & 31;
    if (node >= N) return;

    const float4* base = (const float4*)xlr;
    float4 r0 = base[(size_t)node * 128 + 64 + lane];
    float4 r1 = base[(size_t)node * 128 + 96 + lane];
    float4 a0 = ((const float4*)att)[lane];
    float4 a1 = ((const float4*)att)[32 + lane];

    float mA0 = -1e30f, mA1 = -1e30f, dA0 = 0.f, dA1 = 0.f;
    float mB0 = -1e30f, mB1 = -1e30f, dB0 = 0.f, dB1 = 0.f;
    float4 aA0 = make_float4(0.f,0.f,0.f,0.f), aA1 = make_float4(0.f,0.f,0.f,0.f);
    float4 aB0 = make_float4(0.f,0.f,0.f,0.f), aB1 = make_float4(0.f,0.f,0.f,0.f);

    int beg = g_off[node], end = g_off[node + 1];

    auto process = [&](int s, float& m0, float& m1, float& d0, float& d1,
                       float4& acc0, float4& acc1) {
        float4 l0 = base[(size_t)s * 128 + lane];
        float4 l1 = base[(size_t)s * 128 + 32 + lane];
        float4 e0, e1;
        e0.x = l0.x + r0.x; e0.x = e0.x > 0.f ? e0.x : 0.2f * e0.x;
        e0.y = l0.y + r0.y; e0.y = e0.y > 0.f ? e0.y : 0.2f * e0.y;
        e0.z = l0.z + r0.z; e0.z = e0.z > 0.f ? e0.z : 0.2f * e0.z;
        e0.w = l0.w + r0.w; e0.w = e0.w > 0.f ? e0.w : 0.2f * e0.w;
        e1.x = l1.x + r1.x; e1.x = e1.x > 0.f ? e1.x : 0.2f * e1.x;
        e1.y = l1.y + r1.y; e1.y = e1.y > 0.f ? e1.y : 0.2f * e1.y;
        e1.z = l1.z + r1.z; e1.z = e1.z > 0.f ? e1.z : 0.2f * e1.z;
        e1.w = l1.w + r1.w; e1.w = e1.w > 0.f ? e1.w : 0.2f * e1.w;
        float p0 = e0.x * a0.x + e0.y * a0.y + e0.z * a0.z + e0.w * a0.w;
        float p1 = e1.x * a1.x + e1.y * a1.y + e1.z * a1.z + e1.w * a1.w;
        #pragma unroll
        for (int o = 16; o; o >>= 1) {
            p0 += __shfl_xor_sync(0xffffffffu, p0, o);
            p1 += __shfl_xor_sync(0xffffffffu, p1, o);
        }
        float nm0 = fmaxf(m0, p0);
        float f0 = __expf(m0 - nm0);
        float w0 = __expf(p0 - nm0);
        m0 = nm0;
        d0 = d0 * f0 + w0;
        acc0.x = acc0.x * f0 + w0 * l0.x;
        acc0.y = acc0.y * f0 + w0 * l0.y;
        acc0.z = acc0.z * f0 + w0 * l0.z;
        acc0.w = acc0.w * f0 + w0 * l0.w;
        float nm1 = fmaxf(m1, p1);
        float f1 = __expf(m1 - nm1);
        float w1 = __expf(p1 - nm1);
        m1 = nm1;
        d1 = d1 * f1 + w1;
        acc1.x = acc1.x * f1 + w1 * l1.x;
        acc1.y = acc1.y * f1 + w1 * l1.y;
        acc1.z = acc1.z * f1 + w1 * l1.z;
        acc1.w = acc1.w * f1 + w1 * l1.w;
    };

    int i = beg;
    for (; i + 1 < end; i += 2) {
        int sA = g_esrc[i];
        int sB = g_esrc[i + 1];
        process(sA, mA0, mA1, dA0, dA1, aA0, aA1);
        process(sB, mB0, mB1, dB0, dB1, aB0, aB1);
    }
    if (i < end) process(g_esrc[i], mA0, mA1, dA0, dA1, aA0, aA1);

    {
        float m = fmaxf(mA0, mB0);
        float fA = __expf(mA0 - m), fB = __expf(mB0 - m);
        dA0 = dA0 * fA + dB0 * fB;
        aA0.x = aA0.x * fA + aB0.x * fB;
        aA0.y = aA0.y * fA + aB0.y * fB;
        aA0.z = aA0.z * fA + aB0.z * fB;
        aA0.w = aA0.w * fA + aB0.w * fB;
        m = fmaxf(mA1, mB1);
        fA = __expf(mA1 - m); fB = __expf(mB1 - m);
        dA1 = dA1 * fA + dB1 * fB;
        aA1.x = aA1.x * fA + aB1.x * fB;
        aA1.y = aA1.y * fA + aB1.y * fB;
        aA1.z = aA1.z * fA + aB1.z * fB;
        aA1.w = aA1.w * fA + aB1.w * fB;
    }

    float inv0 = 1.0f / (dA0 + 1e-16f);
    float inv1 = 1.0f / (dA1 + 1e-16f);
    const float4* gb4 = (const float4*)gat_b;
    float4 b0 = gb4[lane];
    float4 b1 = gb4[32 + lane];
    float o0 = aA0.x * inv0 + b0.x, o1 = aA0.y * inv0 + b0.y;
    float o2 = aA0.z * inv0 + b0.z, o3 = aA0.w * inv0 + b0.w;
    float o4 = aA1.x * inv1 + b1.x, o5 = aA1.y * inv1 + b1.y;
    float o6 = aA1.z * inv1 + b1.z, o7 = aA1.w * inv1 + b1.w;

    size_t rb = (size_t)node * 128;
    go[rb + lane * 2]          = pack_h(o0, o1);
    go[rb + lane * 2 + 1]      = pack_h(o2, o3);
    go[rb + 64 + lane * 2]     = pack_h(o4, o5);
    go[rb + 64 + lane * 2 + 1] = pack_h(o6, o7);
}

// ------------------------- launch --------------------------------------------
static inline int pgrid(int ntiles) { return ntiles < PERSIST_BLOCKS ? ntiles : PERSIST_BLOCKS; }

extern "C" void kernel_launch(void* const* d_in, const int* in_sizes, int n_in,
                              void* d_out, int out_size) {
    const float* x_in   = (const float*)d_in[0];
    const void*  edges  = d_in[1];
    const float* ln1_g  = (const float*)d_in[2];
    const float* ln1_b  = (const float*)d_in[3];
    const float* Wl     = (const float*)d_in[4];
    const float* bl     = (const float*)d_in[5];
    const float* Wr     = (const float*)d_in[6];
    const float* br     = (const float*)d_in[7];
    const float* att    = (const float*)d_in[8];
    const float* gat_b  = (const float*)d_in[9];
    const float* projW  = (const float*)d_in[10];
    const float* projb  = (const float*)d_in[11];
    const float* ln2_g  = (const float*)d_in[12];
    const float* ln2_b  = (const float*)d_in[13];
    const float* W1     = (const float*)d_in[14];
    const float* b1     = (const float*)d_in[15];
    const float* W2     = (const float*)d_in[16];
    const float* b2     = (const float*)d_in[17];

    const int N = in_sizes[0] / DIM;
    const int E = in_sizes[1] / 2;
    float* x = (float*)d_out;

    cudaFuncSetAttribute(gemm_kernel<0>, cudaFuncAttributeMaxDynamicSharedMemorySize, GEMM_SMEM);
    cudaFuncSetAttribute(gemm_kernel<1>, cudaFuncAttributeMaxDynamicSharedMemorySize, GEMM_SMEM);
    cudaFuncSetAttribute(gemm_kernel<2>, cudaFuncAttributeMaxDynamicSharedMemorySize, GEMM_SMEM);
    cudaFuncSetAttribute(gemm_kernel<3>, cudaFuncAttributeMaxDynamicSharedMemorySize, GEMM_SMEM3);

    void *p_xlr, *p_h, *p_go, *p_mid, *p_wb, *p_blr;
    cudaGetSymbolAddress(&p_xlr, g_xlr);
    cudaGetSymbolAddress(&p_h, g_h);
    cudaGetSymbolAddress(&p_go, g_go);
    cudaGetSymbolAddress(&p_mid, g_mid);
    cudaGetSymbolAddress(&p_wb, g_wb);
    cudaGetSymbolAddress(&p_blr, g_blr);
    float* xlr = (float*)p_xlr;
    uint32_t* h   = (uint32_t*)p_h;
    uint32_t* go  = (uint32_t*)p_go;
    uint32_t* mid = (uint32_t*)p_mid;
    uint32_t* wb  = (uint32_t*)p_wb;
    float* blr = (float*)p_blr;

    cudaMemcpyAsync(x, x_in, (size_t)N * DIM * sizeof(float), cudaMemcpyDeviceToDevice);

    const int nb = (N + 1023) / 1024;
    detect_kernel<<<1, 256>>>(edges, E, N);
    clear_deg_kernel<<<(N + 255) / 256, 256>>>(N);
    decode_hist_kernel<<<(E + 255) / 256, 256>>>(edges, E);
    scanA_kernel<<<nb, 1024>>>(N);
    scanB_kernel<<<1, 32>>>(nb);
    scanC_kernel<<<(N + 255) / 256, 256>>>(N);
    scatter_kernel<<<(E + 255) / 256, 256>>>(E);

    wconv_all_kernel<<<(2 * LWORDS + 255) / 256, 256>>>(Wl, Wr, projW, W1, W2);
    bconcat_kernel<<<4, 256>>>(bl, br);

    const int ln_blocks = (N + 7) / 8;
    const int mtiles = (N + 127) / 128;

    ln_kernel<<<ln_blocks, 256>>>(x, ln1_g, ln1_b, h, N);

    for (int l = 0; l < 2; l++) {
        size_t off = (size_t)l * LWORDS;
        const uint32_t* wlr = wb + off;
        const uint32_t* pj  = wb + off + 32768;
        const uint32_t* w1  = wb + off + 49152;
        const uint32_t* w2  = wb + off + 81920;
        const float* at_l = att + (size_t)l * HD;
        const float* gb_l = gat_b + (size_t)l * HD;
        const float* pb_l = projb + (size_t)l * DIM;
        const float* b1_l = b1 + (size_t)l * MLPD;
        const float* b2_l = b2 + (size_t)l * DIM;

        // xlr = h @ [Wl|Wr] + blr (fp32 out)
        gemm_kernel<0><<<pgrid(4 * mtiles), 256, GEMM_SMEM>>>(
            h, wlr, blr + (size_t)l * 512, xlr, nullptr,
            nullptr, nullptr, N, DIM, 512);
        // fused GATv2 -> gout single fp16
        gat_node_kernel<<<(N + 7) / 8, 256>>>(xlr, at_l, gb_l, go, N);
        // x += gout @ proj + pb; fused LN2 -> h (fp16)
        gemm_kernel<3><<<pgrid(mtiles), 256, GEMM_SMEM3>>>(
            go, pj, pb_l, x, h,
            ln2_g + (size_t)l * DIM, ln2_b + (size_t)l * DIM, N, HD, DIM);
        // mid = gelu(h @ W1 + b1) -> fp16
        gemm_kernel<2><<<pgrid(4 * mtiles), 256, GEMM_SMEM>>>(
            h, w1, b1_l, nullptr, mid,
            nullptr, nullptr, N, DIM, MLPD);
        // x += mid @ W2 + b2; fused LN1 of next layer
        if (l == 0) {
            gemm_kernel<3><<<pgrid(mtiles), 256, GEMM_SMEM3>>>(
                mid, w2, b2_l, x, h,
                ln1_g + DIM, ln1_b + DIM, N, MLPD, DIM);
        } else {
            gemm_kernel<1><<<pgrid(mtiles), 256, GEMM_SMEM>>>(
                mid, w2, b2_l, x, nullptr,
                nullptr, nullptr, N, MLPD, DIM);
        }
    }
}